// round 1
// baseline (speedup 1.0000x reference)
#include <cuda_runtime.h>
#include <math.h>

#define B_    8
#define CCH   256
#define NPIX  1024
#define HID   1024

static const size_t SZC   = (size_t)B_ * CCH * NPIX;   // 2M floats
static const size_t SZQKV = (size_t)B_ * 3 * CCH * NPIX; // 6M floats
static const size_t SZH   = (size_t)B_ * HID * NPIX;   // 8M floats

// qb(2M) kvb(2M) ln(2M) qkv(6M) att(2M) qn(2M) kvn(2M) h1(8M) h2(8M) = 34M floats
__device__ float g_scratch[34ull * 1024 * 1024];

// ---------------------------------------------------------------------------
// GEMM: Y[b,m,n] = sum_k W[m,k] * X[b,k,n]  (+ optional residual R)
// N = 1024 fixed. Tiles: 64(m) x 64(n) x 16(k). 256 threads, 4x4 microtile.
// ---------------------------------------------------------------------------
__global__ __launch_bounds__(256)
void gemm_kernel(const float* __restrict__ W, const float* __restrict__ X,
                 const float* __restrict__ R, float* __restrict__ Y,
                 int M, int K, size_t ldYb)
{
    __shared__ float Ws[16][64];
    __shared__ float Xs[16][64];
    const int b  = blockIdx.z;
    const int m0 = blockIdx.y * 64;
    const int n0 = blockIdx.x * 64;
    const int t  = threadIdx.x;
    const int tm = t >> 4, tn = t & 15;
    const float* Xb = X + (size_t)b * K * NPIX;

    const int lm  = t >> 2;   // 0..63 (W load row)
    const int lkq = t & 3;    // 0..3  (W load k-quad)
    const int lk  = t >> 4;   // 0..15 (X load k)
    const int lnq = t & 15;   // 0..15 (X load n-quad)

    float acc[4][4];
#pragma unroll
    for (int i = 0; i < 4; i++)
#pragma unroll
        for (int j = 0; j < 4; j++) acc[i][j] = 0.f;

    for (int kk = 0; kk < K; kk += 16) {
        float4 wv  = *(const float4*)(W  + (size_t)(m0 + lm) * K + kk + lkq * 4);
        float4 xv4 = *(const float4*)(Xb + (size_t)(kk + lk) * NPIX + n0 + lnq * 4);
        __syncthreads();
        Ws[lkq * 4 + 0][lm] = wv.x;
        Ws[lkq * 4 + 1][lm] = wv.y;
        Ws[lkq * 4 + 2][lm] = wv.z;
        Ws[lkq * 4 + 3][lm] = wv.w;
        *(float4*)&Xs[lk][lnq * 4] = xv4;
        __syncthreads();
#pragma unroll
        for (int k = 0; k < 16; k++) {
            float4 a = *(float4*)&Ws[k][tm * 4];
            float4 x = *(float4*)&Xs[k][tn * 4];
            acc[0][0] += a.x * x.x; acc[0][1] += a.x * x.y; acc[0][2] += a.x * x.z; acc[0][3] += a.x * x.w;
            acc[1][0] += a.y * x.x; acc[1][1] += a.y * x.y; acc[1][2] += a.y * x.z; acc[1][3] += a.y * x.w;
            acc[2][0] += a.z * x.x; acc[2][1] += a.z * x.y; acc[2][2] += a.z * x.z; acc[2][3] += a.z * x.w;
            acc[3][0] += a.w * x.x; acc[3][1] += a.w * x.y; acc[3][2] += a.w * x.z; acc[3][3] += a.w * x.w;
        }
    }

#pragma unroll
    for (int i = 0; i < 4; i++) {
        int m = m0 + tm * 4 + i;
        size_t off = (size_t)b * ldYb + (size_t)m * NPIX + n0 + tn * 4;
        float4 o;
        o.x = acc[i][0]; o.y = acc[i][1]; o.z = acc[i][2]; o.w = acc[i][3];
        if (R) {
            float4 r = *(const float4*)(R + off);
            o.x += r.x; o.y += r.y; o.z += r.z; o.w += r.w;
        }
        *(float4*)(Y + off) = o;
    }
}

// ---------------------------------------------------------------------------
// Direct conv KSxKS (pad = KS/2), C=256 in/out, 32x32 images.
// Block: 64 out-ch x 64 n (= 2 image rows). BK=8 in-ch per stage; all taps'
// weights staged in smem; per-thread 4x4 with register row-reuse over kx.
// ---------------------------------------------------------------------------
template <int KS>
__global__ __launch_bounds__(256)
void conv_kernel(const float* __restrict__ X, const float* __restrict__ Wt,
                 float* __restrict__ Y)
{
    constexpr int PAD  = KS / 2;
    constexpr int ROWS = 2 + 2 * PAD;
    constexpr int COLS = 32 + 2 * PAD;
    constexpr int TAPS = KS * KS;
    constexpr int BK   = 8;
    extern __shared__ float sm[];
    float* Ws = sm;                       // [BK][64][TAPS]
    float* Xs = sm + BK * 64 * TAPS;      // [BK][ROWS][COLS]

    const int b  = blockIdx.z;
    const int o0 = blockIdx.y * 64;
    const int h0 = blockIdx.x * 2;
    const int t  = threadIdx.x;
    const int tm = t >> 4, tn = t & 15;
    const int nloc = tn * 4;
    const int r = nloc >> 5;
    const int c = nloc & 31;
    const float* Xb = X + (size_t)b * CCH * NPIX;

    float acc[4][4];
#pragma unroll
    for (int i = 0; i < 4; i++)
#pragma unroll
        for (int j = 0; j < 4; j++) acc[i][j] = 0.f;

    for (int kc = 0; kc < CCH; kc += BK) {
        __syncthreads();
        for (int e = t; e < BK * 64 * TAPS; e += 256) {
            int tap = e % TAPS;
            int m   = (e / TAPS) & 63;
            int k   = e / (TAPS * 64);
            Ws[(k * 64 + m) * TAPS + tap] =
                Wt[((size_t)(o0 + m) * CCH + kc + k) * TAPS + tap];
        }
        for (int e = t; e < BK * ROWS * COLS; e += 256) {
            int cc = e % COLS;
            int rr = (e / COLS) % ROWS;
            int k  = e / (COLS * ROWS);
            int hh = h0 + rr - PAD;
            int ww = cc - PAD;
            float v = 0.f;
            if (hh >= 0 && hh < 32 && ww >= 0 && ww < 32)
                v = Xb[(size_t)(kc + k) * NPIX + hh * 32 + ww];
            Xs[(k * ROWS + rr) * COLS + cc] = v;
        }
        __syncthreads();
#pragma unroll
        for (int k = 0; k < BK; k++) {
#pragma unroll
            for (int ky = 0; ky < KS; ky++) {
                float xr[KS + 3];
                const float* xsrow = &Xs[(k * ROWS + r + ky) * COLS + c];
#pragma unroll
                for (int u = 0; u < KS + 3; u++) xr[u] = xsrow[u];
#pragma unroll
                for (int kx = 0; kx < KS; kx++) {
                    int tap = ky * KS + kx;
#pragma unroll
                    for (int i = 0; i < 4; i++) {
                        float wv = Ws[(k * 64 + tm * 4 + i) * TAPS + tap];
                        acc[i][0] += wv * xr[kx + 0];
                        acc[i][1] += wv * xr[kx + 1];
                        acc[i][2] += wv * xr[kx + 2];
                        acc[i][3] += wv * xr[kx + 3];
                    }
                }
            }
        }
    }

    float* Yb = Y + (size_t)b * CCH * NPIX;
#pragma unroll
    for (int i = 0; i < 4; i++) {
        int m = o0 + tm * 4 + i;
        float4 o;
        o.x = acc[i][0]; o.y = acc[i][1]; o.z = acc[i][2]; o.w = acc[i][3];
        *(float4*)(Yb + (size_t)m * NPIX + h0 * 32 + nloc) = o;
    }
}

// ---------------------------------------------------------------------------
// LayerNorm over the channel dim (C=256) of [B,C,N].
// Block handles 32 n-positions; 8 channel-groups x 32 lanes.
// ---------------------------------------------------------------------------
__global__ __launch_bounds__(256)
void ln_kernel(const float* __restrict__ x, const float* __restrict__ w,
               const float* __restrict__ bias, float* __restrict__ y)
{
    const int b  = blockIdx.y;
    const int ln = threadIdx.x & 31;
    const int cg = threadIdx.x >> 5;
    const int n  = blockIdx.x * 32 + ln;
    const float* xb = x + (size_t)b * CCH * NPIX;

    float s = 0.f, s2 = 0.f;
    for (int cch = cg * 32; cch < cg * 32 + 32; cch++) {
        float v = xb[(size_t)cch * NPIX + n];
        s += v; s2 += v * v;
    }
    __shared__ float sb[8][32], sb2[8][32];
    __shared__ float mu[32], istd[32];
    sb[cg][ln] = s; sb2[cg][ln] = s2;
    __syncthreads();
    if (cg == 0) {
        float m = 0.f, m2 = 0.f;
#pragma unroll
        for (int g = 0; g < 8; g++) { m += sb[g][ln]; m2 += sb2[g][ln]; }
        m *= (1.f / 256.f); m2 *= (1.f / 256.f);
        mu[ln]  = m;
        istd[ln] = rsqrtf(m2 - m * m + 1e-5f);
    }
    __syncthreads();
    float mm = mu[ln], is = istd[ln];
    float* yb = y + (size_t)b * CCH * NPIX;
    for (int cch = cg * 32; cch < cg * 32 + 32; cch++) {
        float v = xb[(size_t)cch * NPIX + n];
        yb[(size_t)cch * NPIX + n] = (v - mm) * is * w[cch] + bias[cch];
    }
}

// ---------------------------------------------------------------------------
// Flash-style attention per (b, head, 64-query tile). d=64, N=1024.
// qkv layout: [B][3*256][1024]; heads are 64-channel slices.
// ---------------------------------------------------------------------------
__global__ __launch_bounds__(256)
void attn_kernel(const float* __restrict__ qkv, float* __restrict__ out)
{
    extern __shared__ float sm[];
    float* Qs = sm;                 // [64][64]   (d, q)
    float* Ks = Qs + 4096;          // [64][64]   (d, m)
    float* Vt = Ks + 4096;          // [64][64]   (m, d)  transposed!
    float* Ss = Vt + 4096;          // [64][65]   (q, m)  padded
    float* rmax  = Ss + 64 * 65;
    float* rsum  = rmax + 64;
    float* rcorr = rsum + 64;

    const int b = blockIdx.z, h = blockIdx.y;
    const int q0 = blockIdx.x * 64;
    const float* Q = qkv + ((size_t)b * 768 + h * 64) * NPIX;
    const float* K = qkv + ((size_t)b * 768 + 256 + h * 64) * NPIX;
    const float* V = qkv + ((size_t)b * 768 + 512 + h * 64) * NPIX;
    float* O = out + ((size_t)b * 256 + h * 64) * NPIX;

    const int t = threadIdx.x;
    const int tm = t >> 4, tn = t & 15;

    for (int e = t; e < 1024; e += 256) {
        int d = e >> 4, nq = e & 15;
        *(float4*)&Qs[d * 64 + nq * 4] = *(const float4*)(Q + (size_t)d * NPIX + q0 + nq * 4);
    }
    if (t < 64) { rmax[t] = -1e30f; rsum[t] = 0.f; }

    float acc[4][4];
#pragma unroll
    for (int i = 0; i < 4; i++)
#pragma unroll
        for (int j = 0; j < 4; j++) acc[i][j] = 0.f;

    for (int m0 = 0; m0 < 1024; m0 += 64) {
        __syncthreads();
        for (int e = t; e < 1024; e += 256) {
            int d = e >> 4, nq = e & 15;
            float4 kv = *(const float4*)(K + (size_t)d * NPIX + m0 + nq * 4);
            *(float4*)&Ks[d * 64 + nq * 4] = kv;
            float4 vv = *(const float4*)(V + (size_t)d * NPIX + m0 + nq * 4);
            Vt[(nq * 4 + 0) * 64 + d] = vv.x;
            Vt[(nq * 4 + 1) * 64 + d] = vv.y;
            Vt[(nq * 4 + 2) * 64 + d] = vv.z;
            Vt[(nq * 4 + 3) * 64 + d] = vv.w;
        }
        __syncthreads();

        // S = Q^T K * scale (rows q = tm*4.., cols m = tn*4..)
        float s[4][4];
#pragma unroll
        for (int i = 0; i < 4; i++)
#pragma unroll
            for (int j = 0; j < 4; j++) s[i][j] = 0.f;
#pragma unroll
        for (int d = 0; d < 64; d++) {
            float4 qv = *(float4*)&Qs[d * 64 + tm * 4];
            float4 kv = *(float4*)&Ks[d * 64 + tn * 4];
            s[0][0] += qv.x * kv.x; s[0][1] += qv.x * kv.y; s[0][2] += qv.x * kv.z; s[0][3] += qv.x * kv.w;
            s[1][0] += qv.y * kv.x; s[1][1] += qv.y * kv.y; s[1][2] += qv.y * kv.z; s[1][3] += qv.y * kv.w;
            s[2][0] += qv.z * kv.x; s[2][1] += qv.z * kv.y; s[2][2] += qv.z * kv.z; s[2][3] += qv.z * kv.w;
            s[3][0] += qv.w * kv.x; s[3][1] += qv.w * kv.y; s[3][2] += qv.w * kv.z; s[3][3] += qv.w * kv.w;
        }
#pragma unroll
        for (int i = 0; i < 4; i++)
#pragma unroll
            for (int j = 0; j < 4; j++)
                Ss[(tm * 4 + i) * 65 + tn * 4 + j] = s[i][j] * 0.125f;
        __syncthreads();

        // online softmax: 4 threads per query row
        {
            int row = t >> 2, sub = t & 3;
            float lmx = -1e30f;
#pragma unroll
            for (int j = 0; j < 16; j++)
                lmx = fmaxf(lmx, Ss[row * 65 + sub * 16 + j]);
            lmx = fmaxf(lmx, __shfl_xor_sync(0xffffffffu, lmx, 1));
            lmx = fmaxf(lmx, __shfl_xor_sync(0xffffffffu, lmx, 2));
            float om = rmax[row];
            float nm = fmaxf(om, lmx);
            float ls = 0.f;
#pragma unroll
            for (int j = 0; j < 16; j++) {
                float p = __expf(Ss[row * 65 + sub * 16 + j] - nm);
                Ss[row * 65 + sub * 16 + j] = p;
                ls += p;
            }
            ls += __shfl_xor_sync(0xffffffffu, ls, 1);
            ls += __shfl_xor_sync(0xffffffffu, ls, 2);
            if (sub == 0) {
                float corr = __expf(om - nm);
                rcorr[row] = corr;
                rsum[row] = rsum[row] * corr + ls;
                rmax[row] = nm;
            }
        }
        __syncthreads();

        // O[d][q] = O*corr + sum_m P[q][m] V[m][d]  (d = tm*4.., q = tn*4..)
        float cj0 = rcorr[tn * 4 + 0], cj1 = rcorr[tn * 4 + 1];
        float cj2 = rcorr[tn * 4 + 2], cj3 = rcorr[tn * 4 + 3];
#pragma unroll
        for (int i = 0; i < 4; i++) {
            acc[i][0] *= cj0; acc[i][1] *= cj1; acc[i][2] *= cj2; acc[i][3] *= cj3;
        }
#pragma unroll
        for (int m = 0; m < 64; m++) {
            float4 vv = *(float4*)&Vt[m * 64 + tm * 4];
            float p0 = Ss[(tn * 4 + 0) * 65 + m];
            float p1 = Ss[(tn * 4 + 1) * 65 + m];
            float p2 = Ss[(tn * 4 + 2) * 65 + m];
            float p3 = Ss[(tn * 4 + 3) * 65 + m];
            acc[0][0] += vv.x * p0; acc[0][1] += vv.x * p1; acc[0][2] += vv.x * p2; acc[0][3] += vv.x * p3;
            acc[1][0] += vv.y * p0; acc[1][1] += vv.y * p1; acc[1][2] += vv.y * p2; acc[1][3] += vv.y * p3;
            acc[2][0] += vv.z * p0; acc[2][1] += vv.z * p1; acc[2][2] += vv.z * p2; acc[2][3] += vv.z * p3;
            acc[3][0] += vv.w * p0; acc[3][1] += vv.w * p1; acc[3][2] += vv.w * p2; acc[3][3] += vv.w * p3;
        }
    }

    float i0 = 1.f / rsum[tn * 4 + 0], i1 = 1.f / rsum[tn * 4 + 1];
    float i2 = 1.f / rsum[tn * 4 + 2], i3 = 1.f / rsum[tn * 4 + 3];
#pragma unroll
    for (int i = 0; i < 4; i++) {
        float4 o;
        o.x = acc[i][0] * i0; o.y = acc[i][1] * i1;
        o.z = acc[i][2] * i2; o.w = acc[i][3] * i3;
        *(float4*)(O + (size_t)(tm * 4 + i) * NPIX + q0 + tn * 4) = o;
    }
}

// ---------------------------------------------------------------------------
// Depthwise 3x3 conv + exact GELU. One block per (channel, batch).
// ---------------------------------------------------------------------------
__global__ __launch_bounds__(256)
void dwgelu_kernel(const float* __restrict__ x, const float* __restrict__ wd,
                   float* __restrict__ y)
{
    const int b = blockIdx.y, ch = blockIdx.x;
    const float* xp = x + ((size_t)b * HID + ch) * NPIX;
    __shared__ float tile[34 * 34];
    const int t = threadIdx.x;
    for (int e = t; e < 34 * 34; e += 256) {
        int rr = e / 34, cc = e % 34;
        int hh = rr - 1, ww = cc - 1;
        tile[e] = (hh >= 0 && hh < 32 && ww >= 0 && ww < 32) ? xp[hh * 32 + ww] : 0.f;
    }
    float w9[9];
#pragma unroll
    for (int i = 0; i < 9; i++) w9[i] = wd[(size_t)ch * 9 + i];
    __syncthreads();
    float* yp = y + ((size_t)b * HID + ch) * NPIX;
    for (int e = t; e < 1024; e += 256) {
        int hh = e >> 5, ww = e & 31;
        float a = 0.f;
#pragma unroll
        for (int ky = 0; ky < 3; ky++)
#pragma unroll
            for (int kx = 0; kx < 3; kx++)
                a += w9[ky * 3 + kx] * tile[(hh + ky) * 34 + ww + kx];
        yp[e] = 0.5f * a * (1.f + erff(a * 0.70710678118654752f));
    }
}

// ---------------------------------------------------------------------------
extern "C" void kernel_launch(void* const* d_in, const int* in_sizes, int n_in,
                              void* d_out, int out_size)
{
    const float* aop      = (const float*)d_in[0];
    const float* dop      = (const float*)d_in[1];
    const float* w_qconv  = (const float*)d_in[2];
    const float* w_kvconv = (const float*)d_in[3];
    const float* lnq1_w   = (const float*)d_in[4];
    const float* lnq1_b   = (const float*)d_in[5];
    const float* lnkv1_w  = (const float*)d_in[6];
    const float* lnkv1_b  = (const float*)d_in[7];
    const float* lnq2_w   = (const float*)d_in[8];
    const float* lnq2_b   = (const float*)d_in[9];
    const float* lnkv2_w  = (const float*)d_in[10];
    const float* lnkv2_b  = (const float*)d_in[11];
    const float* lnffn_w  = (const float*)d_in[12];
    const float* lnffn_b  = (const float*)d_in[13];
    const float* saq_qkv  = (const float*)d_in[14];
    const float* saq_proj = (const float*)d_in[15];
    const float* sakv_qkv = (const float*)d_in[16];
    const float* sakv_proj= (const float*)d_in[17];
    const float* ca_q     = (const float*)d_in[18];
    const float* ca_k     = (const float*)d_in[19];
    const float* ca_v     = (const float*)d_in[20];
    const float* ca_proj  = (const float*)d_in[21];
    const float* leff_in  = (const float*)d_in[22];
    const float* leff_dw  = (const float*)d_in[23];
    const float* leff_out = (const float*)d_in[24];
    float* out = (float*)d_out;

    float* S = nullptr;
    cudaGetSymbolAddress((void**)&S, g_scratch);
    float* qb  = S;
    float* kvb = qb  + SZC;
    float* lnb = kvb + SZC;
    float* qkv = lnb + SZC;
    float* att = qkv + SZQKV;
    float* qn  = att + SZC;
    float* kvn = qn  + SZC;
    float* h1  = kvn + SZC;
    float* h2  = h1  + SZH;

    const int CONV5_SM = (8 * 64 * 25 + 8 * 6 * 36) * 4;   // 58112
    const int CONV3_SM = (8 * 64 * 9  + 8 * 4 * 34) * 4;   // 22784
    const int ATTN_SM  = (3 * 4096 + 64 * 65 + 3 * 64) * 4; // 66560
    cudaFuncSetAttribute(conv_kernel<5>, cudaFuncAttributeMaxDynamicSharedMemorySize, CONV5_SM);
    cudaFuncSetAttribute(attn_kernel,    cudaFuncAttributeMaxDynamicSharedMemorySize, ATTN_SM);

    dim3 gconv(16, 4, 8);
    dim3 gln(32, 8);
    dim3 gattn(16, 4, 8);
    const size_t LDC = (size_t)256 * 1024;
    const size_t LDQKV = (size_t)768 * 1024;

    // ---- q branch ----
    conv_kernel<3><<<gconv, 256, CONV3_SM>>>(aop, w_qconv, qb);
    ln_kernel<<<gln, 256>>>(qb, lnq1_w, lnq1_b, lnb);
    gemm_kernel<<<dim3(16, 12, 8), 256>>>(saq_qkv, lnb, nullptr, qkv, 768, 256, LDQKV);
    attn_kernel<<<gattn, 256, ATTN_SM>>>(qkv, att);
    gemm_kernel<<<dim3(16, 4, 8), 256>>>(saq_proj, att, qb, qb, 256, 256, LDC);
    ln_kernel<<<gln, 256>>>(qb, lnq2_w, lnq2_b, qn);

    // ---- kv branch ----
    conv_kernel<5><<<gconv, 256, CONV5_SM>>>(dop, w_kvconv, kvb);
    ln_kernel<<<gln, 256>>>(kvb, lnkv1_w, lnkv1_b, lnb);
    gemm_kernel<<<dim3(16, 12, 8), 256>>>(sakv_qkv, lnb, nullptr, qkv, 768, 256, LDQKV);
    attn_kernel<<<gattn, 256, ATTN_SM>>>(qkv, att);
    gemm_kernel<<<dim3(16, 4, 8), 256>>>(sakv_proj, att, kvb, kvb, 256, 256, LDC);
    ln_kernel<<<gln, 256>>>(kvb, lnkv2_w, lnkv2_b, kvn);

    // ---- cross attention ----
    gemm_kernel<<<dim3(16, 4, 8), 256>>>(ca_q, qn,  nullptr, qkv,              256, 256, LDQKV);
    gemm_kernel<<<dim3(16, 4, 8), 256>>>(ca_k, kvn, nullptr, qkv + 256 * 1024, 256, 256, LDQKV);
    gemm_kernel<<<dim3(16, 4, 8), 256>>>(ca_v, kvn, nullptr, qkv + 512 * 1024, 256, 256, LDQKV);
    attn_kernel<<<gattn, 256, ATTN_SM>>>(qkv, att);
    gemm_kernel<<<dim3(16, 4, 8), 256>>>(ca_proj, att, qb, out, 256, 256, LDC);

    // ---- LeFF ----
    ln_kernel<<<gln, 256>>>(out, lnffn_w, lnffn_b, lnb);
    gemm_kernel<<<dim3(16, 16, 8), 256>>>(leff_in, lnb, nullptr, h1, 1024, 256, (size_t)1024 * 1024);
    dwgelu_kernel<<<dim3(1024, 8), 256>>>(h1, leff_dw, h2);
    gemm_kernel<<<dim3(16, 4, 8), 256>>>(leff_out, h2, out, out, 256, 1024, LDC);
}

// round 5
// speedup vs baseline: 1.9273x; 1.9273x over previous
#include <cuda_runtime.h>
#include <math.h>
#include <stdint.h>

#define B_    8
#define CCH   256
#define NPIX  1024
#define HID   1024
#define NTOK  (B_ * NPIX)   // 8192

// scratch layout (floats)
static const size_t IC_SZ  = (size_t)B_ * NPIX * 6400;   // 52.4M (im2col, shared 3x3/5x5)
static const size_t C_SZ   = (size_t)NTOK * CCH;         // 2M
static const size_t QKV_SZ = (size_t)NTOK * 768;         // 6M
static const size_t H_SZ   = (size_t)NTOK * HID;         // 8M
__device__ float g_scratch[92ull * 1024 * 1024];

extern __shared__ char dyn_smem[];

__device__ __forceinline__ float to_tf32(float x) {
    float r;
    asm("cvt.rna.tf32.f32 %0, %1;" : "=f"(r) : "f"(x));
    return r;
}

// ---------------------------------------------------------------------------
// tf32 mma.sync GEMM: Y[tok, n] = sum_k A[tok, k] * W[n, k]  (+ optional R)
// Block tile 128(tok) x 128(n) x 32(k). 256 threads = 8 warps, each 64x32
// via 4x4 grid of m16n8k8. Smem [128][36] pad-4 -> conflict-free frag loads.
// grid: (tokTiles=8, Nout/128, B).
// transY: store Y channel-major [B][Nout][1024] (final NCHW output)
// ---------------------------------------------------------------------------
__global__ __launch_bounds__(256, 1)
void gemm_tc(const float* __restrict__ A, size_t ldA,
             const float* __restrict__ Wt,
             const float* __restrict__ R, size_t ldR,
             float* __restrict__ Y, size_t ldY,
             int K, int transY)
{
    __shared__ float As[128][36];
    __shared__ float Bs[128][36];

    const int t = threadIdx.x;
    const int wid = t >> 5, lane = t & 31;
    const int g = lane >> 2, tig = lane & 3;       // groupID, thread-in-group
    const int warp_m = (wid & 1) * 64;
    const int warp_n = (wid >> 1) * 32;

    const float* Ab = A  + (size_t)blockIdx.z * NPIX * ldA + (size_t)blockIdx.x * 128 * ldA;
    const float* Bb = Wt + (size_t)blockIdx.y * 128 * (size_t)K;

    // global-load mapping: 4 float4 per thread per tile
    const int r0l = t >> 3;            // 0..31  (+32 per i)
    const int q0l = t & 7;             // quad 0..7

    float acc[4][4][4];
#pragma unroll
    for (int im = 0; im < 4; im++)
#pragma unroll
        for (int in = 0; in < 4; in++)
#pragma unroll
            for (int c = 0; c < 4; c++) acc[im][in][c] = 0.f;

    const int nk = K >> 5;
    float4 av[4], bv[4];

    // prefetch tile 0
#pragma unroll
    for (int i = 0; i < 4; i++) {
        const int r = r0l + i * 32;
        av[i] = *(const float4*)(Ab + (size_t)r * ldA + q0l * 4);
        bv[i] = *(const float4*)(Bb + (size_t)r * K   + q0l * 4);
    }

    for (int kt = 0; kt < nk; kt++) {
        // stage to smem with tf32 rounding
#pragma unroll
        for (int i = 0; i < 4; i++) {
            const int r = r0l + i * 32;
            As[r][q0l * 4 + 0] = to_tf32(av[i].x);
            As[r][q0l * 4 + 1] = to_tf32(av[i].y);
            As[r][q0l * 4 + 2] = to_tf32(av[i].z);
            As[r][q0l * 4 + 3] = to_tf32(av[i].w);
            Bs[r][q0l * 4 + 0] = to_tf32(bv[i].x);
            Bs[r][q0l * 4 + 1] = to_tf32(bv[i].y);
            Bs[r][q0l * 4 + 2] = to_tf32(bv[i].z);
            Bs[r][q0l * 4 + 3] = to_tf32(bv[i].w);
        }
        __syncthreads();

        if (kt + 1 < nk) {
            const int kk = (kt + 1) << 5;
#pragma unroll
            for (int i = 0; i < 4; i++) {
                const int r = r0l + i * 32;
                av[i] = *(const float4*)(Ab + (size_t)r * ldA + kk + q0l * 4);
                bv[i] = *(const float4*)(Bb + (size_t)r * K   + kk + q0l * 4);
            }
        }

#pragma unroll
        for (int ks = 0; ks < 4; ks++) {
            const int k0 = ks * 8;
            uint32_t af[4][4], bf[4][2];
#pragma unroll
            for (int im = 0; im < 4; im++) {
                const int rm = warp_m + im * 16;
                af[im][0] = __float_as_uint(As[rm + g][k0 + tig]);
                af[im][1] = __float_as_uint(As[rm + g + 8][k0 + tig]);
                af[im][2] = __float_as_uint(As[rm + g][k0 + tig + 4]);
                af[im][3] = __float_as_uint(As[rm + g + 8][k0 + tig + 4]);
            }
#pragma unroll
            for (int in = 0; in < 4; in++) {
                const int cn = warp_n + in * 8;
                bf[in][0] = __float_as_uint(Bs[cn + g][k0 + tig]);
                bf[in][1] = __float_as_uint(Bs[cn + g][k0 + tig + 4]);
            }
#pragma unroll
            for (int im = 0; im < 4; im++)
#pragma unroll
                for (int in = 0; in < 4; in++) {
                    asm volatile(
                        "mma.sync.aligned.m16n8k8.row.col.f32.tf32.tf32.f32 "
                        "{%0,%1,%2,%3}, {%4,%5,%6,%7}, {%8,%9}, {%0,%1,%2,%3};"
                        : "+f"(acc[im][in][0]), "+f"(acc[im][in][1]),
                          "+f"(acc[im][in][2]), "+f"(acc[im][in][3])
                        : "r"(af[im][0]), "r"(af[im][1]), "r"(af[im][2]), "r"(af[im][3]),
                          "r"(bf[in][0]), "r"(bf[in][1]));
                }
        }
        __syncthreads();
    }

    // epilogue
    const int b = blockIdx.z;
    if (!transY) {
        float* Yb = Y + (size_t)b * NPIX * ldY;
        const float* Rb = R ? R + (size_t)b * NPIX * ldR : (const float*)0;
#pragma unroll
        for (int im = 0; im < 4; im++) {
#pragma unroll
            for (int half = 0; half < 2; half++) {
                const int tok = blockIdx.x * 128 + warp_m + im * 16 + g + half * 8;
#pragma unroll
                for (int in = 0; in < 4; in++) {
                    const int col = blockIdx.y * 128 + warp_n + in * 8 + tig * 2;
                    float2 v;
                    v.x = acc[im][in][half * 2 + 0];
                    v.y = acc[im][in][half * 2 + 1];
                    if (Rb) {
                        float2 rr = *(const float2*)(Rb + (size_t)tok * ldR + col);
                        v.x += rr.x; v.y += rr.y;
                    }
                    *(float2*)(Yb + (size_t)tok * ldY + col) = v;
                }
            }
        }
    } else {
        float* Yb = Y + (size_t)b * ldY * NPIX;
        const float* Rb = R ? R + (size_t)b * NPIX * ldR : (const float*)0;
#pragma unroll
        for (int im = 0; im < 4; im++) {
#pragma unroll
            for (int half = 0; half < 2; half++) {
                const int tokl = warp_m + im * 16 + g + half * 8;
                const int tok  = blockIdx.x * 128 + tokl;
#pragma unroll
                for (int in = 0; in < 4; in++) {
                    const int col = blockIdx.y * 128 + warp_n + in * 8 + tig * 2;
                    float v0 = acc[im][in][half * 2 + 0];
                    float v1 = acc[im][in][half * 2 + 1];
                    if (Rb) {
                        float2 rr = *(const float2*)(Rb + (size_t)tok * ldR + col);
                        v0 += rr.x; v1 += rr.y;
                    }
                    Yb[(size_t)(col + 0) * NPIX + tok] = v0;
                    Yb[(size_t)(col + 1) * NPIX + tok] = v1;
                }
            }
        }
    }
}

// ---------------------------------------------------------------------------
// im2col: NCHW input -> [B][1024 tok][C*KS*KS]  (k = c*KS^2 + ky*KS + kx)
// grid: (C/64, 32 rows, B).  block 256.
// ---------------------------------------------------------------------------
template <int KS>
__global__ __launch_bounds__(256)
void im2col_kernel(const float* __restrict__ in, float* __restrict__ out)
{
    constexpr int PAD  = KS / 2;
    constexpr int TAPS = KS * KS;
    constexpr int KTOT = CCH * TAPS;
    __shared__ float smv[64 * KS * 36];
    const int c0 = blockIdx.x * 64;
    const int h  = blockIdx.y;
    const int b  = blockIdx.z;
    const int t  = threadIdx.x;

    for (int e = t; e < 64 * KS * 36; e += 256) {
        const int cc = e % 36;
        const int r  = (e / 36) % KS;
        const int c  = e / (36 * KS);
        const int hh = h + r - PAD;
        const int ww = cc - PAD;
        float v = 0.f;
        if (hh >= 0 && hh < 32 && ww >= 0 && ww < 32)
            v = in[((size_t)b * CCH + c0 + c) * NPIX + hh * 32 + ww];
        smv[(c * KS + r) * 36 + cc] = v;
    }
    __syncthreads();
    for (int e = t; e < 32 * 64 * TAPS; e += 256) {
        const int w   = e / (64 * TAPS);
        const int rem = e % (64 * TAPS);
        const int c   = rem / TAPS;
        const int tap = rem % TAPS;
        const int ky  = tap / KS, kx = tap % KS;
        out[((size_t)b * NPIX + h * 32 + w) * KTOT + (size_t)(c0 + c) * TAPS + tap] =
            smv[(c * KS + ky) * 36 + (w + kx)];
    }
}

// ---------------------------------------------------------------------------
// LayerNorm over channels, token-major [8192][256]. Warp per token.
// ---------------------------------------------------------------------------
__global__ __launch_bounds__(256)
void ln_kernel(const float* __restrict__ x, const float* __restrict__ w,
               const float* __restrict__ bs, float* __restrict__ y)
{
    const int warp = threadIdx.x >> 5, lane = threadIdx.x & 31;
    const size_t tok = (size_t)blockIdx.x * 8 + warp;
    const float* xr = x + tok * CCH;
    float4 v0 = *(const float4*)(xr + lane * 4);
    float4 v1 = *(const float4*)(xr + 128 + lane * 4);
    float s  = v0.x + v0.y + v0.z + v0.w + v1.x + v1.y + v1.z + v1.w;
    float s2 = v0.x*v0.x + v0.y*v0.y + v0.z*v0.z + v0.w*v0.w
             + v1.x*v1.x + v1.y*v1.y + v1.z*v1.z + v1.w*v1.w;
#pragma unroll
    for (int o = 16; o > 0; o >>= 1) {
        s  += __shfl_xor_sync(0xffffffffu, s,  o);
        s2 += __shfl_xor_sync(0xffffffffu, s2, o);
    }
    const float mu = s * (1.f / 256.f);
    const float is = rsqrtf(s2 * (1.f / 256.f) - mu * mu + 1e-5f);
    float4 w0 = *(const float4*)(w + lane * 4);
    float4 w1 = *(const float4*)(w + 128 + lane * 4);
    float4 b0 = *(const float4*)(bs + lane * 4);
    float4 b1 = *(const float4*)(bs + 128 + lane * 4);
    float* yr = y + tok * CCH;
    float4 o0, o1;
    o0.x = (v0.x - mu) * is * w0.x + b0.x; o0.y = (v0.y - mu) * is * w0.y + b0.y;
    o0.z = (v0.z - mu) * is * w0.z + b0.z; o0.w = (v0.w - mu) * is * w0.w + b0.w;
    o1.x = (v1.x - mu) * is * w1.x + b1.x; o1.y = (v1.y - mu) * is * w1.y + b1.y;
    o1.z = (v1.z - mu) * is * w1.z + b1.z; o1.w = (v1.w - mu) * is * w1.w + b1.w;
    *(float4*)(yr + lane * 4) = o0;
    *(float4*)(yr + 128 + lane * 4) = o1;
}

// ---------------------------------------------------------------------------
// Flash attention fp32, token-major. qkv [B][1024][768], out [B][1024][256].
// grid: (16 qtiles, 4 heads, B). block 256.
// Qs/Ks stride 64 (float4-aligned columns); Ss padded to 65 (scalar access).
// ---------------------------------------------------------------------------
__global__ __launch_bounds__(256)
void attn_kernel(const float* __restrict__ qkv, float* __restrict__ out)
{
    float* sm = (float*)dyn_smem;
    float* Qs = sm;                 // [64][64] (d, q)
    float* Ks = Qs + 64 * 64;       // [64][64] (d, m)
    float* Vt = Ks + 64 * 64;       // [64][64] (m, d)
    float* Ss = Vt + 64 * 64;       // [64][65] (q, m)  scalar access only
    float* rmax  = Ss + 64 * 65;
    float* rsum  = rmax + 64;
    float* rcorr = rsum + 64;

    const int b = blockIdx.z, h = blockIdx.y;
    const int q0 = blockIdx.x * 64;
    const float* base = qkv + (size_t)b * NPIX * 768;
    const int hq = h * 64;

    const int t = threadIdx.x;
    const int tm = t & 15;
    const int tn = t >> 4;

    for (int e = t; e < 1024; e += 256) {
        const int tok = e >> 4, dq = e & 15;
        float4 qv = *(const float4*)(base + (size_t)(q0 + tok) * 768 + hq + dq * 4);
        Qs[(dq * 4 + 0) * 64 + tok] = qv.x;
        Qs[(dq * 4 + 1) * 64 + tok] = qv.y;
        Qs[(dq * 4 + 2) * 64 + tok] = qv.z;
        Qs[(dq * 4 + 3) * 64 + tok] = qv.w;
    }
    if (t < 64) { rmax[t] = -1e30f; rsum[t] = 0.f; }

    float acc[4][4];
#pragma unroll
    for (int i = 0; i < 4; i++)
#pragma unroll
        for (int j = 0; j < 4; j++) acc[i][j] = 0.f;

    for (int m0 = 0; m0 < 1024; m0 += 64) {
        __syncthreads();
        for (int e = t; e < 1024; e += 256) {
            const int tok = e >> 4, dq = e & 15;
            float4 kv = *(const float4*)(base + (size_t)(m0 + tok) * 768 + 256 + hq + dq * 4);
            Ks[(dq * 4 + 0) * 64 + tok] = kv.x;
            Ks[(dq * 4 + 1) * 64 + tok] = kv.y;
            Ks[(dq * 4 + 2) * 64 + tok] = kv.z;
            Ks[(dq * 4 + 3) * 64 + tok] = kv.w;
            float4 vv = *(const float4*)(base + (size_t)(m0 + tok) * 768 + 512 + hq + dq * 4);
            *(float4*)&Vt[tok * 64 + dq * 4] = vv;
        }
        __syncthreads();

        float s[4][4];
#pragma unroll
        for (int i = 0; i < 4; i++)
#pragma unroll
            for (int j = 0; j < 4; j++) s[i][j] = 0.f;
#pragma unroll
        for (int d = 0; d < 64; d++) {
            float4 qv = *(float4*)&Qs[d * 64 + tn * 4];
            float4 kv = *(float4*)&Ks[d * 64 + tm * 4];
            s[0][0] += qv.x * kv.x; s[0][1] += qv.x * kv.y; s[0][2] += qv.x * kv.z; s[0][3] += qv.x * kv.w;
            s[1][0] += qv.y * kv.x; s[1][1] += qv.y * kv.y; s[1][2] += qv.y * kv.z; s[1][3] += qv.y * kv.w;
            s[2][0] += qv.z * kv.x; s[2][1] += qv.z * kv.y; s[2][2] += qv.z * kv.z; s[2][3] += qv.z * kv.w;
            s[3][0] += qv.w * kv.x; s[3][1] += qv.w * kv.y; s[3][2] += qv.w * kv.z; s[3][3] += qv.w * kv.w;
        }
#pragma unroll
        for (int i = 0; i < 4; i++)
#pragma unroll
            for (int j = 0; j < 4; j++)
                Ss[(tn * 4 + i) * 65 + tm * 4 + j] = s[i][j] * 0.125f;
        __syncthreads();

        {   // online softmax: 4 threads per query row
            const int row = t >> 2, sub = t & 3;
            float lmx = -1e30f;
#pragma unroll
            for (int j = 0; j < 16; j++)
                lmx = fmaxf(lmx, Ss[row * 65 + sub * 16 + j]);
            lmx = fmaxf(lmx, __shfl_xor_sync(0xffffffffu, lmx, 1));
            lmx = fmaxf(lmx, __shfl_xor_sync(0xffffffffu, lmx, 2));
            const float om = rmax[row];
            const float nm = fmaxf(om, lmx);
            float ls = 0.f;
#pragma unroll
            for (int j = 0; j < 16; j++) {
                float p = __expf(Ss[row * 65 + sub * 16 + j] - nm);
                Ss[row * 65 + sub * 16 + j] = p;
                ls += p;
            }
            ls += __shfl_xor_sync(0xffffffffu, ls, 1);
            ls += __shfl_xor_sync(0xffffffffu, ls, 2);
            if (sub == 0) {
                const float corr = __expf(om - nm);
                rcorr[row] = corr;
                rsum[row] = rsum[row] * corr + ls;
                rmax[row] = nm;
            }
        }
        __syncthreads();

        const float cj0 = rcorr[tn * 4 + 0], cj1 = rcorr[tn * 4 + 1];
        const float cj2 = rcorr[tn * 4 + 2], cj3 = rcorr[tn * 4 + 3];
#pragma unroll
        for (int i = 0; i < 4; i++) {
            acc[i][0] *= cj0; acc[i][1] *= cj1; acc[i][2] *= cj2; acc[i][3] *= cj3;
        }
#pragma unroll
        for (int m = 0; m < 64; m++) {
            float4 vv = *(float4*)&Vt[m * 64 + tm * 4];
            const float p0 = Ss[(tn * 4 + 0) * 65 + m];
            const float p1 = Ss[(tn * 4 + 1) * 65 + m];
            const float p2 = Ss[(tn * 4 + 2) * 65 + m];
            const float p3 = Ss[(tn * 4 + 3) * 65 + m];
            acc[0][0] += vv.x * p0; acc[0][1] += vv.x * p1; acc[0][2] += vv.x * p2; acc[0][3] += vv.x * p3;
            acc[1][0] += vv.y * p0; acc[1][1] += vv.y * p1; acc[1][2] += vv.y * p2; acc[1][3] += vv.y * p3;
            acc[2][0] += vv.z * p0; acc[2][1] += vv.z * p1; acc[2][2] += vv.z * p2; acc[2][3] += vv.z * p3;
            acc[3][0] += vv.w * p0; acc[3][1] += vv.w * p1; acc[3][2] += vv.w * p2; acc[3][3] += vv.w * p3;
        }
    }

    float* ob = out + (size_t)b * NPIX * CCH;
#pragma unroll
    for (int j = 0; j < 4; j++) {
        const int q = tn * 4 + j;
        const float inv = 1.f / rsum[q];
        float4 o;
        o.x = acc[0][j] * inv; o.y = acc[1][j] * inv;
        o.z = acc[2][j] * inv; o.w = acc[3][j] * inv;
        *(float4*)(ob + (size_t)(q0 + q) * CCH + hq + tm * 4) = o;
    }
}

// ---------------------------------------------------------------------------
// Depthwise 3x3 + exact GELU, token-major [8192][1024].
// grid: (32 ch-groups, 4 row-groups, B). block 256 (thread ch = t&31 fixed).
// ---------------------------------------------------------------------------
__global__ __launch_bounds__(256)
void dwgelu_kernel(const float* __restrict__ x, const float* __restrict__ wd,
                   float* __restrict__ y)
{
    __shared__ float tile[10][34][32];
    const int c0 = blockIdx.x * 32;
    const int r0 = blockIdx.y * 8;
    const int b  = blockIdx.z;
    const int t  = threadIdx.x;
    const int ch = t & 31;

    for (int e = t; e < 10 * 34 * 32; e += 256) {
        const int cc  = e & 31;
        const int col = (e >> 5) % 34;
        const int r   = e / (34 * 32);
        const int hh = r0 + r - 1, ww = col - 1;
        float v = 0.f;
        if (hh >= 0 && hh < 32 && ww >= 0 && ww < 32)
            v = x[((size_t)b * NPIX + hh * 32 + ww) * HID + c0 + cc];
        tile[r][col][cc] = v;
    }
    float w9[9];
#pragma unroll
    for (int i = 0; i < 9; i++) w9[i] = wd[(size_t)(c0 + ch) * 9 + i];
    __syncthreads();

    for (int e = t; e < 8 * 32 * 32; e += 256) {
        const int w = (e >> 5) & 31;
        const int r = e >> 10;
        float a = 0.f;
#pragma unroll
        for (int ky = 0; ky < 3; ky++)
#pragma unroll
            for (int kx = 0; kx < 3; kx++)
                a += w9[ky * 3 + kx] * tile[r + ky][w + kx][ch];
        y[((size_t)b * NPIX + (r0 + r) * 32 + w) * HID + c0 + ch] =
            0.5f * a * (1.f + erff(a * 0.70710678118654752f));
    }
}

// ---------------------------------------------------------------------------
extern "C" void kernel_launch(void* const* d_in, const int* in_sizes, int n_in,
                              void* d_out, int out_size)
{
    const float* aop      = (const float*)d_in[0];
    const float* dop      = (const float*)d_in[1];
    const float* w_qconv  = (const float*)d_in[2];
    const float* w_kvconv = (const float*)d_in[3];
    const float* lnq1_w   = (const float*)d_in[4];
    const float* lnq1_b   = (const float*)d_in[5];
    const float* lnkv1_w  = (const float*)d_in[6];
    const float* lnkv1_b  = (const float*)d_in[7];
    const float* lnq2_w   = (const float*)d_in[8];
    const float* lnq2_b   = (const float*)d_in[9];
    const float* lnkv2_w  = (const float*)d_in[10];
    const float* lnkv2_b  = (const float*)d_in[11];
    const float* lnffn_w  = (const float*)d_in[12];
    const float* lnffn_b  = (const float*)d_in[13];
    const float* saq_qkv  = (const float*)d_in[14];
    const float* saq_proj = (const float*)d_in[15];
    const float* sakv_qkv = (const float*)d_in[16];
    const float* sakv_proj= (const float*)d_in[17];
    const float* ca_q     = (const float*)d_in[18];
    const float* ca_k     = (const float*)d_in[19];
    const float* ca_v     = (const float*)d_in[20];
    const float* ca_proj  = (const float*)d_in[21];
    const float* leff_in  = (const float*)d_in[22];
    const float* leff_dw  = (const float*)d_in[23];
    const float* leff_out = (const float*)d_in[24];
    float* out = (float*)d_out;

    float* S = nullptr;
    cudaGetSymbolAddress((void**)&S, g_scratch);
    float* ic   = S;
    float* qb   = ic   + IC_SZ;
    float* kvb  = qb   + C_SZ;
    float* lnb  = kvb  + C_SZ;
    float* qn   = lnb  + C_SZ;
    float* kvn  = qn   + C_SZ;
    float* att  = kvn  + C_SZ;
    float* xbuf = att  + C_SZ;
    float* qkv  = xbuf + C_SZ;
    float* h1   = qkv  + QKV_SZ;
    float* h2   = h1   + H_SZ;

    const int ATTN_SM = (4 * 64 * 64 + 64 * 65 + 192) * 4;  // 82688
    cudaFuncSetAttribute(attn_kernel, cudaFuncAttributeMaxDynamicSharedMemorySize, ATTN_SM);

    const dim3 g256(8, 2, B_), g768(8, 6, B_), g1024t(8, 8, B_);
    const dim3 gattn(16, 4, B_);
    const dim3 gi2c(4, 32, B_);
    const dim3 gdw(32, 4, B_);

    // ---- q branch ----
    im2col_kernel<3><<<gi2c, 256>>>(aop, ic);
    gemm_tc<<<g256, 256>>>(ic, 2304, w_qconv, nullptr, 0, qb, 256, 2304, 0);
    ln_kernel<<<1024, 256>>>(qb, lnq1_w, lnq1_b, lnb);
    gemm_tc<<<g768, 256>>>(lnb, 256, saq_qkv, nullptr, 0, qkv, 768, 256, 0);
    attn_kernel<<<gattn, 256, ATTN_SM>>>(qkv, att);
    gemm_tc<<<g256, 256>>>(att, 256, saq_proj, qb, 256, qb, 256, 256, 0);
    ln_kernel<<<1024, 256>>>(qb, lnq2_w, lnq2_b, qn);

    // ---- kv branch ----
    im2col_kernel<5><<<gi2c, 256>>>(dop, ic);
    gemm_tc<<<g256, 256>>>(ic, 6400, w_kvconv, nullptr, 0, kvb, 256, 6400, 0);
    ln_kernel<<<1024, 256>>>(kvb, lnkv1_w, lnkv1_b, lnb);
    gemm_tc<<<g768, 256>>>(lnb, 256, sakv_qkv, nullptr, 0, qkv, 768, 256, 0);
    attn_kernel<<<gattn, 256, ATTN_SM>>>(qkv, att);
    gemm_tc<<<g256, 256>>>(att, 256, sakv_proj, kvb, 256, kvb, 256, 256, 0);
    ln_kernel<<<1024, 256>>>(kvb, lnkv2_w, lnkv2_b, kvn);

    // ---- cross attention ----
    gemm_tc<<<g256, 256>>>(qn,  256, ca_q, nullptr, 0, qkv,       768, 256, 0);
    gemm_tc<<<g256, 256>>>(kvn, 256, ca_k, nullptr, 0, qkv + 256, 768, 256, 0);
    gemm_tc<<<g256, 256>>>(kvn, 256, ca_v, nullptr, 0, qkv + 512, 768, 256, 0);
    attn_kernel<<<gattn, 256, ATTN_SM>>>(qkv, att);
    gemm_tc<<<g256, 256>>>(att, 256, ca_proj, qb, 256, xbuf, 256, 256, 0);

    // ---- LeFF ----
    ln_kernel<<<1024, 256>>>(xbuf, lnffn_w, lnffn_b, lnb);
    gemm_tc<<<g1024t, 256>>>(lnb, 256, leff_in, nullptr, 0, h1, 1024, 256, 0);
    dwgelu_kernel<<<gdw, 256>>>(h1, leff_dw, h2);
    gemm_tc<<<g256, 256>>>(h2, 1024, leff_out, xbuf, 256, out, 256, 1024, 1);
}

// round 7
// speedup vs baseline: 3.0724x; 1.5942x over previous
#include <cuda_runtime.h>
#include <math.h>
#include <stdint.h>

#define B_    8
#define CCH   256
#define NPIX  1024
#define HID   1024
#define NTOK  (B_ * NPIX)   // 8192

// scratch layout (floats)
static const size_t IC_SZ  = (size_t)B_ * NPIX * 6400;   // 52.4M (im2col, shared 3x3/5x5)
static const size_t C_SZ   = (size_t)NTOK * CCH;         // 2M
static const size_t QKV_SZ = (size_t)NTOK * 768;         // 6M
static const size_t H_SZ   = (size_t)NTOK * HID;         // 8M
__device__ float g_scratch[92ull * 1024 * 1024];

extern __shared__ char dyn_smem[];

__device__ __forceinline__ float to_tf32(float x) {
    float r;
    asm("cvt.rna.tf32.f32 %0, %1;" : "=f"(r) : "f"(x));
    return r;
}

#define MMA_TF32(acc, a0, a1, a2, a3, b0, b1) \
    asm volatile( \
        "mma.sync.aligned.m16n8k8.row.col.f32.tf32.tf32.f32 " \
        "{%0,%1,%2,%3}, {%4,%5,%6,%7}, {%8,%9}, {%0,%1,%2,%3};" \
        : "+f"((acc)[0]), "+f"((acc)[1]), "+f"((acc)[2]), "+f"((acc)[3]) \
        : "r"(a0), "r"(a1), "r"(a2), "r"(a3), "r"(b0), "r"(b1))

// ---------------------------------------------------------------------------
// tf32 mma.sync GEMM: Y[tok, n] = sum_k A[tok, k] * W[n, k]  (+ optional R)
// Block tile 128(tok) x 128(n) x 32(k). 256 threads = 8 warps, each 64x32
// via 4x4 grid of m16n8k8. Smem [128][36] pad-4 -> conflict-free frag loads.
// grid: (tokTiles=8, Nout/128, B).
// transY: store Y channel-major [B][Nout][1024] (final NCHW output)
// ---------------------------------------------------------------------------
__global__ __launch_bounds__(256, 1)
void gemm_tc(const float* __restrict__ A, size_t ldA,
             const float* __restrict__ Wt,
             const float* __restrict__ R, size_t ldR,
             float* __restrict__ Y, size_t ldY,
             int K, int transY)
{
    __shared__ float As[128][36];
    __shared__ float Bs[128][36];

    const int t = threadIdx.x;
    const int wid = t >> 5, lane = t & 31;
    const int g = lane >> 2, tig = lane & 3;       // groupID, thread-in-group
    const int warp_m = (wid & 1) * 64;
    const int warp_n = (wid >> 1) * 32;

    const float* Ab = A  + (size_t)blockIdx.z * NPIX * ldA + (size_t)blockIdx.x * 128 * ldA;
    const float* Bb = Wt + (size_t)blockIdx.y * 128 * (size_t)K;

    const int r0l = t >> 3;            // 0..31  (+32 per i)
    const int q0l = t & 7;             // quad 0..7

    float acc[4][4][4];
#pragma unroll
    for (int im = 0; im < 4; im++)
#pragma unroll
        for (int in = 0; in < 4; in++)
#pragma unroll
            for (int c = 0; c < 4; c++) acc[im][in][c] = 0.f;

    const int nk = K >> 5;
    float4 av[4], bv[4];

#pragma unroll
    for (int i = 0; i < 4; i++) {
        const int r = r0l + i * 32;
        av[i] = *(const float4*)(Ab + (size_t)r * ldA + q0l * 4);
        bv[i] = *(const float4*)(Bb + (size_t)r * K   + q0l * 4);
    }

    for (int kt = 0; kt < nk; kt++) {
#pragma unroll
        for (int i = 0; i < 4; i++) {
            const int r = r0l + i * 32;
            As[r][q0l * 4 + 0] = to_tf32(av[i].x);
            As[r][q0l * 4 + 1] = to_tf32(av[i].y);
            As[r][q0l * 4 + 2] = to_tf32(av[i].z);
            As[r][q0l * 4 + 3] = to_tf32(av[i].w);
            Bs[r][q0l * 4 + 0] = to_tf32(bv[i].x);
            Bs[r][q0l * 4 + 1] = to_tf32(bv[i].y);
            Bs[r][q0l * 4 + 2] = to_tf32(bv[i].z);
            Bs[r][q0l * 4 + 3] = to_tf32(bv[i].w);
        }
        __syncthreads();

        if (kt + 1 < nk) {
            const int kk = (kt + 1) << 5;
#pragma unroll
            for (int i = 0; i < 4; i++) {
                const int r = r0l + i * 32;
                av[i] = *(const float4*)(Ab + (size_t)r * ldA + kk + q0l * 4);
                bv[i] = *(const float4*)(Bb + (size_t)r * K   + kk + q0l * 4);
            }
        }

#pragma unroll
        for (int ks = 0; ks < 4; ks++) {
            const int k0 = ks * 8;
            uint32_t af[4][4], bf[4][2];
#pragma unroll
            for (int im = 0; im < 4; im++) {
                const int rm = warp_m + im * 16;
                af[im][0] = __float_as_uint(As[rm + g][k0 + tig]);
                af[im][1] = __float_as_uint(As[rm + g + 8][k0 + tig]);
                af[im][2] = __float_as_uint(As[rm + g][k0 + tig + 4]);
                af[im][3] = __float_as_uint(As[rm + g + 8][k0 + tig + 4]);
            }
#pragma unroll
            for (int in = 0; in < 4; in++) {
                const int cn = warp_n + in * 8;
                bf[in][0] = __float_as_uint(Bs[cn + g][k0 + tig]);
                bf[in][1] = __float_as_uint(Bs[cn + g][k0 + tig + 4]);
            }
#pragma unroll
            for (int im = 0; im < 4; im++)
#pragma unroll
                for (int in = 0; in < 4; in++)
                    MMA_TF32(acc[im][in], af[im][0], af[im][1], af[im][2], af[im][3],
                             bf[in][0], bf[in][1]);
        }
        __syncthreads();
    }

    const int b = blockIdx.z;
    if (!transY) {
        float* Yb = Y + (size_t)b * NPIX * ldY;
        const float* Rb = R ? R + (size_t)b * NPIX * ldR : (const float*)0;
#pragma unroll
        for (int im = 0; im < 4; im++) {
#pragma unroll
            for (int half = 0; half < 2; half++) {
                const int tok = blockIdx.x * 128 + warp_m + im * 16 + g + half * 8;
#pragma unroll
                for (int in = 0; in < 4; in++) {
                    const int col = blockIdx.y * 128 + warp_n + in * 8 + tig * 2;
                    float2 v;
                    v.x = acc[im][in][half * 2 + 0];
                    v.y = acc[im][in][half * 2 + 1];
                    if (Rb) {
                        float2 rr = *(const float2*)(Rb + (size_t)tok * ldR + col);
                        v.x += rr.x; v.y += rr.y;
                    }
                    *(float2*)(Yb + (size_t)tok * ldY + col) = v;
                }
            }
        }
    } else {
        float* Yb = Y + (size_t)b * ldY * NPIX;
        const float* Rb = R ? R + (size_t)b * NPIX * ldR : (const float*)0;
#pragma unroll
        for (int im = 0; im < 4; im++) {
#pragma unroll
            for (int half = 0; half < 2; half++) {
                const int tok = blockIdx.x * 128 + warp_m + im * 16 + g + half * 8;
#pragma unroll
                for (int in = 0; in < 4; in++) {
                    const int col = blockIdx.y * 128 + warp_n + in * 8 + tig * 2;
                    float v0 = acc[im][in][half * 2 + 0];
                    float v1 = acc[im][in][half * 2 + 1];
                    if (Rb) {
                        float2 rr = *(const float2*)(Rb + (size_t)tok * ldR + col);
                        v0 += rr.x; v1 += rr.y;
                    }
                    Yb[(size_t)(col + 0) * NPIX + tok] = v0;
                    Yb[(size_t)(col + 1) * NPIX + tok] = v1;
                }
            }
        }
    }
}

// ---------------------------------------------------------------------------
// im2col: NCHW input -> [B][1024 tok][C*KS*KS]  (k = c*KS^2 + ky*KS + kx)
// ---------------------------------------------------------------------------
template <int KS>
__global__ __launch_bounds__(256)
void im2col_kernel(const float* __restrict__ in, float* __restrict__ out)
{
    constexpr int PAD  = KS / 2;
    constexpr int TAPS = KS * KS;
    constexpr int KTOT = CCH * TAPS;
    __shared__ float smv[64 * KS * 36];
    const int c0 = blockIdx.x * 64;
    const int h  = blockIdx.y;
    const int b  = blockIdx.z;
    const int t  = threadIdx.x;

    for (int e = t; e < 64 * KS * 36; e += 256) {
        const int cc = e % 36;
        const int r  = (e / 36) % KS;
        const int c  = e / (36 * KS);
        const int hh = h + r - PAD;
        const int ww = cc - PAD;
        float v = 0.f;
        if (hh >= 0 && hh < 32 && ww >= 0 && ww < 32)
            v = in[((size_t)b * CCH + c0 + c) * NPIX + hh * 32 + ww];
        smv[(c * KS + r) * 36 + cc] = v;
    }
    __syncthreads();
    for (int e = t; e < 32 * 64 * TAPS; e += 256) {
        const int w   = e / (64 * TAPS);
        const int rem = e % (64 * TAPS);
        const int c   = rem / TAPS;
        const int tap = rem % TAPS;
        const int ky  = tap / KS, kx = tap % KS;
        out[((size_t)b * NPIX + h * 32 + w) * KTOT + (size_t)(c0 + c) * TAPS + tap] =
            smv[(c * KS + ky) * 36 + (w + kx)];
    }
}

// ---------------------------------------------------------------------------
// LayerNorm over channels, token-major [8192][256]. Warp per token.
// ---------------------------------------------------------------------------
__global__ __launch_bounds__(256)
void ln_kernel(const float* __restrict__ x, const float* __restrict__ w,
               const float* __restrict__ bs, float* __restrict__ y)
{
    const int warp = threadIdx.x >> 5, lane = threadIdx.x & 31;
    const size_t tok = (size_t)blockIdx.x * 8 + warp;
    const float* xr = x + tok * CCH;
    float4 v0 = *(const float4*)(xr + lane * 4);
    float4 v1 = *(const float4*)(xr + 128 + lane * 4);
    float s  = v0.x + v0.y + v0.z + v0.w + v1.x + v1.y + v1.z + v1.w;
    float s2 = v0.x*v0.x + v0.y*v0.y + v0.z*v0.z + v0.w*v0.w
             + v1.x*v1.x + v1.y*v1.y + v1.z*v1.z + v1.w*v1.w;
#pragma unroll
    for (int o = 16; o > 0; o >>= 1) {
        s  += __shfl_xor_sync(0xffffffffu, s,  o);
        s2 += __shfl_xor_sync(0xffffffffu, s2, o);
    }
    const float mu = s * (1.f / 256.f);
    const float is = rsqrtf(s2 * (1.f / 256.f) - mu * mu + 1e-5f);
    float4 w0 = *(const float4*)(w + lane * 4);
    float4 w1 = *(const float4*)(w + 128 + lane * 4);
    float4 b0 = *(const float4*)(bs + lane * 4);
    float4 b1 = *(const float4*)(bs + 128 + lane * 4);
    float* yr = y + tok * CCH;
    float4 o0, o1;
    o0.x = (v0.x - mu) * is * w0.x + b0.x; o0.y = (v0.y - mu) * is * w0.y + b0.y;
    o0.z = (v0.z - mu) * is * w0.z + b0.z; o0.w = (v0.w - mu) * is * w0.w + b0.w;
    o1.x = (v1.x - mu) * is * w1.x + b1.x; o1.y = (v1.y - mu) * is * w1.y + b1.y;
    o1.z = (v1.z - mu) * is * w1.z + b1.z; o1.w = (v1.w - mu) * is * w1.w + b1.w;
    *(float4*)(yr + lane * 4) = o0;
    *(float4*)(yr + 128 + lane * 4) = o1;
}

// ---------------------------------------------------------------------------
// Flash attention, tf32 mma. qkv [B][1024][768] token-major,
// out [B][1024][256] token-major.
// Block: 128 queries, 8 warps (16 q-rows each, warp-private softmax state).
// K/V tiles of 64 keys, double buffered. grid: (8 qtiles, 4 heads, B).
// ---------------------------------------------------------------------------
__global__ __launch_bounds__(256, 1)
void attn_kernel(const float* __restrict__ qkv, float* __restrict__ out)
{
    float* sm = (float*)dyn_smem;
    float* Qs = sm;                      // [128][68]
    float* Ks = Qs + 128 * 68;           // [2][64][68]
    float* Vt = Ks + 2 * 64 * 68;        // [2][64][68]  (d, key)
    float* Ps = Vt + 2 * 64 * 68;        // [128][68]

    const int b = blockIdx.z, h = blockIdx.y;
    const int q0 = blockIdx.x * 128;
    const int hq = h * 64;
    const float* base = qkv + (size_t)b * NPIX * 768;

    const int t = threadIdx.x;
    const int wid = t >> 5, lane = t & 31;
    const int g = lane >> 2, tig = lane & 3;
    const int w16 = wid * 16;

    // load Q tile (tf32)
#pragma unroll
    for (int i = 0; i < 8; i++) {
        const int e = t + i * 256;
        const int r = e >> 4, c = e & 15;
        float4 v = *(const float4*)(base + (size_t)(q0 + r) * 768 + hq + c * 4);
        Qs[r * 68 + c * 4 + 0] = to_tf32(v.x);
        Qs[r * 68 + c * 4 + 1] = to_tf32(v.y);
        Qs[r * 68 + c * 4 + 2] = to_tf32(v.z);
        Qs[r * 68 + c * 4 + 3] = to_tf32(v.w);
    }

    float oc[8][4];
#pragma unroll
    for (int n = 0; n < 8; n++)
#pragma unroll
        for (int c = 0; c < 4; c++) oc[n][c] = 0.f;
    float m0r = -1e30f, m1r = -1e30f, l0r = 0.f, l1r = 0.f;

    const int rkv = t & 63;                 // V-load row (per lane)
    float4 kvr[4], vvr[4];
    // prefetch tile 0
#pragma unroll
    for (int i = 0; i < 4; i++) {
        const int e = t + i * 256;
        const int rk = e >> 4, ck = e & 15;
        kvr[i] = *(const float4*)(base + (size_t)rk * 768 + 256 + hq + ck * 4);
        const int cv = (t >> 6) + i * 4;
        vvr[i] = *(const float4*)(base + (size_t)rkv * 768 + 512 + hq + cv * 4);
    }
    // stage tile 0 into buffer 0
    {
        float* Kb = Ks;
        float* Vb = Vt;
#pragma unroll
        for (int i = 0; i < 4; i++) {
            const int e = t + i * 256;
            const int rk = e >> 4, ck = e & 15;
            Kb[rk * 68 + ck * 4 + 0] = to_tf32(kvr[i].x);
            Kb[rk * 68 + ck * 4 + 1] = to_tf32(kvr[i].y);
            Kb[rk * 68 + ck * 4 + 2] = to_tf32(kvr[i].z);
            Kb[rk * 68 + ck * 4 + 3] = to_tf32(kvr[i].w);
            const int cv = (t >> 6) + i * 4;
            Vb[(cv * 4 + 0) * 68 + rkv] = to_tf32(vvr[i].x);
            Vb[(cv * 4 + 1) * 68 + rkv] = to_tf32(vvr[i].y);
            Vb[(cv * 4 + 2) * 68 + rkv] = to_tf32(vvr[i].z);
            Vb[(cv * 4 + 3) * 68 + rkv] = to_tf32(vvr[i].w);
        }
    }
    __syncthreads();

    for (int tile = 0; tile < 16; tile++) {
        const int buf = tile & 1;
        float* Kb = Ks + buf * 64 * 68;
        float* Vb = Vt + buf * 64 * 68;

        if (tile < 15) {
            const size_t m0 = (size_t)(tile + 1) * 64;
#pragma unroll
            for (int i = 0; i < 4; i++) {
                const int e = t + i * 256;
                const int rk = e >> 4, ck = e & 15;
                kvr[i] = *(const float4*)(base + (m0 + rk) * 768 + 256 + hq + ck * 4);
                const int cv = (t >> 6) + i * 4;
                vvr[i] = *(const float4*)(base + (m0 + rkv) * 768 + 512 + hq + cv * 4);
            }
        }

        // S = Q K^T
        float s[8][4];
#pragma unroll
        for (int n = 0; n < 8; n++)
#pragma unroll
            for (int c = 0; c < 4; c++) s[n][c] = 0.f;
#pragma unroll
        for (int ks = 0; ks < 8; ks++) {
            const int k0 = ks * 8;
            const uint32_t a0 = __float_as_uint(Qs[(w16 + g) * 68 + k0 + tig]);
            const uint32_t a1 = __float_as_uint(Qs[(w16 + g + 8) * 68 + k0 + tig]);
            const uint32_t a2 = __float_as_uint(Qs[(w16 + g) * 68 + k0 + tig + 4]);
            const uint32_t a3 = __float_as_uint(Qs[(w16 + g + 8) * 68 + k0 + tig + 4]);
#pragma unroll
            for (int n = 0; n < 8; n++) {
                const uint32_t b0 = __float_as_uint(Kb[(n * 8 + g) * 68 + k0 + tig]);
                const uint32_t b1 = __float_as_uint(Kb[(n * 8 + g) * 68 + k0 + tig + 4]);
                MMA_TF32(s[n], a0, a1, a2, a3, b0, b1);
            }
        }

        // online softmax (rows g and g+8, quad-reduced)
        float t0 = -1e30f, t1 = -1e30f;
#pragma unroll
        for (int n = 0; n < 8; n++) {
            s[n][0] *= 0.125f; s[n][1] *= 0.125f;
            s[n][2] *= 0.125f; s[n][3] *= 0.125f;
            t0 = fmaxf(t0, fmaxf(s[n][0], s[n][1]));
            t1 = fmaxf(t1, fmaxf(s[n][2], s[n][3]));
        }
        t0 = fmaxf(t0, __shfl_xor_sync(0xffffffffu, t0, 1));
        t0 = fmaxf(t0, __shfl_xor_sync(0xffffffffu, t0, 2));
        t1 = fmaxf(t1, __shfl_xor_sync(0xffffffffu, t1, 1));
        t1 = fmaxf(t1, __shfl_xor_sync(0xffffffffu, t1, 2));
        const float nm0 = fmaxf(m0r, t0), nm1 = fmaxf(m1r, t1);
        const float cr0 = __expf(m0r - nm0), cr1 = __expf(m1r - nm1);
        m0r = nm0; m1r = nm1;
        float ls0 = 0.f, ls1 = 0.f;
#pragma unroll
        for (int n = 0; n < 8; n++) {
            const float p0 = __expf(s[n][0] - nm0);
            const float p1 = __expf(s[n][1] - nm0);
            const float p2 = __expf(s[n][2] - nm1);
            const float p3 = __expf(s[n][3] - nm1);
            ls0 += p0 + p1; ls1 += p2 + p3;
            float2 pa; pa.x = to_tf32(p0); pa.y = to_tf32(p1);
            float2 pb; pb.x = to_tf32(p2); pb.y = to_tf32(p3);
            *(float2*)&Ps[(w16 + g) * 68 + n * 8 + tig * 2] = pa;
            *(float2*)&Ps[(w16 + g + 8) * 68 + n * 8 + tig * 2] = pb;
        }
        ls0 += __shfl_xor_sync(0xffffffffu, ls0, 1);
        ls0 += __shfl_xor_sync(0xffffffffu, ls0, 2);
        ls1 += __shfl_xor_sync(0xffffffffu, ls1, 1);
        ls1 += __shfl_xor_sync(0xffffffffu, ls1, 2);
        l0r = l0r * cr0 + ls0;
        l1r = l1r * cr1 + ls1;
#pragma unroll
        for (int n = 0; n < 8; n++) {
            oc[n][0] *= cr0; oc[n][1] *= cr0;
            oc[n][2] *= cr1; oc[n][3] *= cr1;
        }
        __syncwarp();

        // O += P V   (A = Ps rows of this warp, B = Vt[d][key])
#pragma unroll
        for (int ks = 0; ks < 8; ks++) {
            const int k0 = ks * 8;
            const uint32_t a0 = __float_as_uint(Ps[(w16 + g) * 68 + k0 + tig]);
            const uint32_t a1 = __float_as_uint(Ps[(w16 + g + 8) * 68 + k0 + tig]);
            const uint32_t a2 = __float_as_uint(Ps[(w16 + g) * 68 + k0 + tig + 4]);
            const uint32_t a3 = __float_as_uint(Ps[(w16 + g + 8) * 68 + k0 + tig + 4]);
#pragma unroll
            for (int n = 0; n < 8; n++) {
                const uint32_t b0 = __float_as_uint(Vb[(n * 8 + g) * 68 + k0 + tig]);
                const uint32_t b1 = __float_as_uint(Vb[(n * 8 + g) * 68 + k0 + tig + 4]);
                MMA_TF32(oc[n], a0, a1, a2, a3, b0, b1);
            }
        }

        if (tile < 15) {
            __syncthreads();
            float* Kn = Ks + (buf ^ 1) * 64 * 68;
            float* Vn = Vt + (buf ^ 1) * 64 * 68;
#pragma unroll
            for (int i = 0; i < 4; i++) {
                const int e = t + i * 256;
                const int rk = e >> 4, ck = e & 15;
                Kn[rk * 68 + ck * 4 + 0] = to_tf32(kvr[i].x);
                Kn[rk * 68 + ck * 4 + 1] = to_tf32(kvr[i].y);
                Kn[rk * 68 + ck * 4 + 2] = to_tf32(kvr[i].z);
                Kn[rk * 68 + ck * 4 + 3] = to_tf32(kvr[i].w);
                const int cv = (t >> 6) + i * 4;
                Vn[(cv * 4 + 0) * 68 + rkv] = to_tf32(vvr[i].x);
                Vn[(cv * 4 + 1) * 68 + rkv] = to_tf32(vvr[i].y);
                Vn[(cv * 4 + 2) * 68 + rkv] = to_tf32(vvr[i].z);
                Vn[(cv * 4 + 3) * 68 + rkv] = to_tf32(vvr[i].w);
            }
            __syncthreads();
        }
    }

    const float i0 = 1.f / l0r, i1 = 1.f / l1r;
    float* ob = out + (size_t)b * NPIX * CCH;
#pragma unroll
    for (int n = 0; n < 8; n++) {
        float2 v0; v0.x = oc[n][0] * i0; v0.y = oc[n][1] * i0;
        float2 v1; v1.x = oc[n][2] * i1; v1.y = oc[n][3] * i1;
        *(float2*)(ob + (size_t)(q0 + w16 + g) * CCH + hq + n * 8 + tig * 2) = v0;
        *(float2*)(ob + (size_t)(q0 + w16 + g + 8) * CCH + hq + n * 8 + tig * 2) = v1;
    }
}

// ---------------------------------------------------------------------------
// Depthwise 3x3 + exact GELU, token-major [8192][1024].
// ---------------------------------------------------------------------------
__global__ __launch_bounds__(256)
void dwgelu_kernel(const float* __restrict__ x, const float* __restrict__ wd,
                   float* __restrict__ y)
{
    __shared__ float tile[10][34][32];
    const int c0 = blockIdx.x * 32;
    const int r0 = blockIdx.y * 8;
    const int b  = blockIdx.z;
    const int t  = threadIdx.x;
    const int ch = t & 31;

    for (int e = t; e < 10 * 34 * 32; e += 256) {
        const int cc  = e & 31;
        const int col = (e >> 5) % 34;
        const int r   = e / (34 * 32);
        const int hh = r0 + r - 1, ww = col - 1;
        float v = 0.f;
        if (hh >= 0 && hh < 32 && ww >= 0 && ww < 32)
            v = x[((size_t)b * NPIX + hh * 32 + ww) * HID + c0 + cc];
        tile[r][col][cc] = v;
    }
    float w9[9];
#pragma unroll
    for (int i = 0; i < 9; i++) w9[i] = wd[(size_t)(c0 + ch) * 9 + i];
    __syncthreads();

    for (int e = t; e < 8 * 32 * 32; e += 256) {
        const int w = (e >> 5) & 31;
        const int r = e >> 10;
        float a = 0.f;
#pragma unroll
        for (int ky = 0; ky < 3; ky++)
#pragma unroll
            for (int kx = 0; kx < 3; kx++)
                a += w9[ky * 3 + kx] * tile[r + ky][w + kx][ch];
        y[((size_t)b * NPIX + (r0 + r) * 32 + w) * HID + c0 + ch] =
            0.5f * a * (1.f + erff(a * 0.70710678118654752f));
    }
}

// ---------------------------------------------------------------------------
extern "C" void kernel_launch(void* const* d_in, const int* in_sizes, int n_in,
                              void* d_out, int out_size)
{
    const float* aop      = (const float*)d_in[0];
    const float* dop      = (const float*)d_in[1];
    const float* w_qconv  = (const float*)d_in[2];
    const float* w_kvconv = (const float*)d_in[3];
    const float* lnq1_w   = (const float*)d_in[4];
    const float* lnq1_b   = (const float*)d_in[5];
    const float* lnkv1_w  = (const float*)d_in[6];
    const float* lnkv1_b  = (const float*)d_in[7];
    const float* lnq2_w   = (const float*)d_in[8];
    const float* lnq2_b   = (const float*)d_in[9];
    const float* lnkv2_w  = (const float*)d_in[10];
    const float* lnkv2_b  = (const float*)d_in[11];
    const float* lnffn_w  = (const float*)d_in[12];
    const float* lnffn_b  = (const float*)d_in[13];
    const float* saq_qkv  = (const float*)d_in[14];
    const float* saq_proj = (const float*)d_in[15];
    const float* sakv_qkv = (const float*)d_in[16];
    const float* sakv_proj= (const float*)d_in[17];
    const float* ca_q     = (const float*)d_in[18];
    const float* ca_k     = (const float*)d_in[19];
    const float* ca_v     = (const float*)d_in[20];
    const float* ca_proj  = (const float*)d_in[21];
    const float* leff_in  = (const float*)d_in[22];
    const float* leff_dw  = (const float*)d_in[23];
    const float* leff_out = (const float*)d_in[24];
    float* out = (float*)d_out;

    float* S = nullptr;
    cudaGetSymbolAddress((void**)&S, g_scratch);
    float* ic   = S;
    float* qb   = ic   + IC_SZ;
    float* kvb  = qb   + C_SZ;
    float* lnb  = kvb  + C_SZ;
    float* qn   = lnb  + C_SZ;
    float* kvn  = qn   + C_SZ;
    float* att  = kvn  + C_SZ;
    float* xbuf = att  + C_SZ;
    float* qkv  = xbuf + C_SZ;
    float* h1   = qkv  + QKV_SZ;
    float* h2   = h1   + H_SZ;

    const int ATTN_SM = (128 * 68 + 2 * 64 * 68 + 2 * 64 * 68 + 128 * 68) * 4; // 139264
    cudaFuncSetAttribute(attn_kernel, cudaFuncAttributeMaxDynamicSharedMemorySize, ATTN_SM);

    const dim3 g256(8, 2, B_), g768(8, 6, B_), g1024t(8, 8, B_);
    const dim3 gattn(8, 4, B_);
    const dim3 gi2c(4, 32, B_);
    const dim3 gdw(32, 4, B_);

    // ---- q branch ----
    im2col_kernel<3><<<gi2c, 256>>>(aop, ic);
    gemm_tc<<<g256, 256>>>(ic, 2304, w_qconv, nullptr, 0, qb, 256, 2304, 0);
    ln_kernel<<<1024, 256>>>(qb, lnq1_w, lnq1_b, lnb);
    gemm_tc<<<g768, 256>>>(lnb, 256, saq_qkv, nullptr, 0, qkv, 768, 256, 0);
    attn_kernel<<<gattn, 256, ATTN_SM>>>(qkv, att);
    gemm_tc<<<g256, 256>>>(att, 256, saq_proj, qb, 256, qb, 256, 256, 0);
    ln_kernel<<<1024, 256>>>(qb, lnq2_w, lnq2_b, qn);

    // ---- kv branch ----
    im2col_kernel<5><<<gi2c, 256>>>(dop, ic);
    gemm_tc<<<g256, 256>>>(ic, 6400, w_kvconv, nullptr, 0, kvb, 256, 6400, 0);
    ln_kernel<<<1024, 256>>>(kvb, lnkv1_w, lnkv1_b, lnb);
    gemm_tc<<<g768, 256>>>(lnb, 256, sakv_qkv, nullptr, 0, qkv, 768, 256, 0);
    attn_kernel<<<gattn, 256, ATTN_SM>>>(qkv, att);
    gemm_tc<<<g256, 256>>>(att, 256, sakv_proj, kvb, 256, kvb, 256, 256, 0);
    ln_kernel<<<1024, 256>>>(kvb, lnkv2_w, lnkv2_b, kvn);

    // ---- cross attention ----
    gemm_tc<<<g256, 256>>>(qn,  256, ca_q, nullptr, 0, qkv,       768, 256, 0);
    gemm_tc<<<g256, 256>>>(kvn, 256, ca_k, nullptr, 0, qkv + 256, 768, 256, 0);
    gemm_tc<<<g256, 256>>>(kvn, 256, ca_v, nullptr, 0, qkv + 512, 768, 256, 0);
    attn_kernel<<<gattn, 256, ATTN_SM>>>(qkv, att);
    gemm_tc<<<g256, 256>>>(att, 256, ca_proj, qb, 256, xbuf, 256, 256, 0);

    // ---- LeFF ----
    ln_kernel<<<1024, 256>>>(xbuf, lnffn_w, lnffn_b, lnb);
    gemm_tc<<<g1024t, 256>>>(lnb, 256, leff_in, nullptr, 0, h1, 1024, 256, 0);
    dwgelu_kernel<<<gdw, 256>>>(h1, leff_dw, h2);
    gemm_tc<<<g256, 256>>>(h2, 1024, leff_out, xbuf, 256, out, 256, 1024, 1);
}

// round 8
// speedup vs baseline: 3.1301x; 1.0188x over previous
#include <cuda_runtime.h>
#include <math.h>
#include <stdint.h>

#define B_    8
#define CCH   256
#define NPIX  1024
#define HID   1024
#define NTOK  (B_ * NPIX)   // 8192

// scratch layout (floats)
static const size_t IC_SZ  = (size_t)B_ * NPIX * 6400;   // 52.4M
static const size_t C_SZ   = (size_t)NTOK * CCH;         // 2M
static const size_t QKV_SZ = (size_t)NTOK * 768;         // 6M
static const size_t H_SZ   = (size_t)NTOK * HID;         // 8M
__device__ float g_scratch[92ull * 1024 * 1024];

extern __shared__ char dyn_smem[];

__device__ __forceinline__ float to_tf32(float x) {
    float r;
    asm("cvt.rna.tf32.f32 %0, %1;" : "=f"(r) : "f"(x));
    return r;
}
__device__ __forceinline__ uint32_t smem_addr(const void* p) {
    return (uint32_t)__cvta_generic_to_shared(p);
}
__device__ __forceinline__ void cp16(uint32_t dst, const void* src) {
    asm volatile("cp.async.ca.shared.global [%0], [%1], 16;" :: "r"(dst), "l"(src));
}
// k-permutation within each 8-block: newpos(k) = (k&3)*2 + ((k>>2)&1)
__device__ __forceinline__ int permk(int k) {
    return (k & ~7) | (((k & 3) << 1) | ((k >> 2) & 1));
}

#define MMA_TF32(acc, a0, a1, a2, a3, b0, b1) \
    asm volatile( \
        "mma.sync.aligned.m16n8k8.row.col.f32.tf32.tf32.f32 " \
        "{%0,%1,%2,%3}, {%4,%5,%6,%7}, {%8,%9}, {%0,%1,%2,%3};" \
        : "+f"((acc)[0]), "+f"((acc)[1]), "+f"((acc)[2]), "+f"((acc)[3]) \
        : "r"(a0), "r"(a1), "r"(a2), "r"(a3), "r"(b0), "r"(b1))

// ---------------------------------------------------------------------------
// weight prep: tf32-round + k-permute copy. [M][K] layout, K % 8 == 0.
// ---------------------------------------------------------------------------
__global__ __launch_bounds__(256)
void prep_w(const float* __restrict__ src, float* __restrict__ dst, int total)
{
    int i = blockIdx.x * 256 + threadIdx.x;
    if (i < total) {
        int pk = (i & ~7) | (((i & 3) << 1) | ((i >> 2) & 1));
        dst[pk] = to_tf32(src[i]);
    }
}

// ---------------------------------------------------------------------------
// tf32 mma.sync GEMM on PRE-PERMUTED tf32 inputs (A and Wt both [rows][K] with
// k-permuted columns). Y (+residual R) in NORMAL fp32 layout.
// Block 128x128x32, 8 warps (64x32 each), cp.async double buffer, smem
// [2][128][40] per matrix (stride 40 => conflict-free LDS.64 frags).
// ---------------------------------------------------------------------------
__global__ __launch_bounds__(256, 2)
void gemm_tc(const float* __restrict__ A, size_t ldA,
             const float* __restrict__ Wt,
             const float* __restrict__ R, size_t ldR,
             float* __restrict__ Y, size_t ldY,
             int K, int transY)
{
    float* As = (float*)dyn_smem;        // [2][128*40]
    float* Bs = As + 2 * 5120;           // [2][128*40]

    const int t = threadIdx.x;
    const int wid = t >> 5, lane = t & 31;
    const int g = lane >> 2, tig = lane & 3;
    const int warp_m = (wid & 1) * 64;
    const int warp_n = (wid >> 1) * 32;
    const int r0l = t >> 3, q0l = t & 7;

    const float* Ab = A  + (size_t)blockIdx.z * NPIX * ldA + (size_t)blockIdx.x * 128 * ldA;
    const float* Bb = Wt + (size_t)blockIdx.y * 128 * (size_t)K;

    const uint32_t sA = smem_addr(As), sB = smem_addr(Bs);

    float acc[4][4][4];
#pragma unroll
    for (int im = 0; im < 4; im++)
#pragma unroll
        for (int in = 0; in < 4; in++)
#pragma unroll
            for (int c = 0; c < 4; c++) acc[im][in][c] = 0.f;

    const int nk = K >> 5;

    // issue chunk 0
#pragma unroll
    for (int i = 0; i < 4; i++) {
        const int r = r0l + i * 32;
        cp16(sA + (uint32_t)(r * 40 + q0l * 4) * 4, Ab + (size_t)r * ldA + q0l * 4);
        cp16(sB + (uint32_t)(r * 40 + q0l * 4) * 4, Bb + (size_t)r * K   + q0l * 4);
    }
    asm volatile("cp.async.commit_group;");

    for (int c = 0; c < nk; c++) {
        asm volatile("cp.async.wait_group 0;");
        __syncthreads();
        if (c + 1 < nk) {
            const int kk = (c + 1) << 5;
            const uint32_t boff = (uint32_t)((c + 1) & 1) * 5120;
#pragma unroll
            for (int i = 0; i < 4; i++) {
                const int r = r0l + i * 32;
                cp16(sA + (boff + r * 40 + q0l * 4) * 4, Ab + (size_t)r * ldA + kk + q0l * 4);
                cp16(sB + (boff + r * 40 + q0l * 4) * 4, Bb + (size_t)r * K   + kk + q0l * 4);
            }
            asm volatile("cp.async.commit_group;");
        }
        const float* Ac = As + (c & 1) * 5120;
        const float* Bc = Bs + (c & 1) * 5120;
#pragma unroll
        for (int ks = 0; ks < 4; ks++) {
            const int k0 = ks * 8;
            float2 au[4], al[4];
#pragma unroll
            for (int im = 0; im < 4; im++) {
                au[im] = *(const float2*)&Ac[(warp_m + im * 16 + g) * 40 + k0 + 2 * tig];
                al[im] = *(const float2*)&Ac[(warp_m + im * 16 + g + 8) * 40 + k0 + 2 * tig];
            }
#pragma unroll
            for (int in = 0; in < 4; in++) {
                const float2 bv = *(const float2*)&Bc[(warp_n + in * 8 + g) * 40 + k0 + 2 * tig];
#pragma unroll
                for (int im = 0; im < 4; im++) {
                    MMA_TF32(acc[im][in],
                             __float_as_uint(au[im].x), __float_as_uint(al[im].x),
                             __float_as_uint(au[im].y), __float_as_uint(al[im].y),
                             __float_as_uint(bv.x), __float_as_uint(bv.y));
                }
            }
        }
    }

    const int b = blockIdx.z;
    if (!transY) {
        float* Yb = Y + (size_t)b * NPIX * ldY;
        const float* Rb = R ? R + (size_t)b * NPIX * ldR : (const float*)0;
#pragma unroll
        for (int im = 0; im < 4; im++) {
#pragma unroll
            for (int half = 0; half < 2; half++) {
                const int tok = blockIdx.x * 128 + warp_m + im * 16 + g + half * 8;
#pragma unroll
                for (int in = 0; in < 4; in++) {
                    const int col = blockIdx.y * 128 + warp_n + in * 8 + tig * 2;
                    float2 v;
                    v.x = acc[im][in][half * 2 + 0];
                    v.y = acc[im][in][half * 2 + 1];
                    if (Rb) {
                        float2 rr = *(const float2*)(Rb + (size_t)tok * ldR + col);
                        v.x += rr.x; v.y += rr.y;
                    }
                    *(float2*)(Yb + (size_t)tok * ldY + col) = v;
                }
            }
        }
    } else {
        float* Yb = Y + (size_t)b * ldY * NPIX;
        const float* Rb = R ? R + (size_t)b * NPIX * ldR : (const float*)0;
#pragma unroll
        for (int im = 0; im < 4; im++) {
#pragma unroll
            for (int half = 0; half < 2; half++) {
                const int tok = blockIdx.x * 128 + warp_m + im * 16 + g + half * 8;
#pragma unroll
                for (int in = 0; in < 4; in++) {
                    const int col = blockIdx.y * 128 + warp_n + in * 8 + tig * 2;
                    float v0 = acc[im][in][half * 2 + 0];
                    float v1 = acc[im][in][half * 2 + 1];
                    if (Rb) {
                        float2 rr = *(const float2*)(Rb + (size_t)tok * ldR + col);
                        v0 += rr.x; v1 += rr.y;
                    }
                    Yb[(size_t)(col + 0) * NPIX + tok] = v0;
                    Yb[(size_t)(col + 1) * NPIX + tok] = v1;
                }
            }
        }
    }
}

// ---------------------------------------------------------------------------
// im2col: NCHW -> [B][1024 tok][C*KS*KS], tf32-rounded, k-permuted.
// ---------------------------------------------------------------------------
template <int KS>
__global__ __launch_bounds__(256)
void im2col_kernel(const float* __restrict__ in, float* __restrict__ out)
{
    constexpr int PAD  = KS / 2;
    constexpr int TAPS = KS * KS;
    constexpr int KTOT = CCH * TAPS;
    __shared__ float smv[64 * KS * 36];
    const int c0 = blockIdx.x * 64;
    const int h  = blockIdx.y;
    const int b  = blockIdx.z;
    const int t  = threadIdx.x;

    for (int e = t; e < 64 * KS * 36; e += 256) {
        const int cc = e % 36;
        const int r  = (e / 36) % KS;
        const int c  = e / (36 * KS);
        const int hh = h + r - PAD;
        const int ww = cc - PAD;
        float v = 0.f;
        if (hh >= 0 && hh < 32 && ww >= 0 && ww < 32)
            v = in[((size_t)b * CCH + c0 + c) * NPIX + hh * 32 + ww];
        smv[(c * KS + r) * 36 + cc] = v;
    }
    __syncthreads();
    for (int e = t; e < 32 * 64 * TAPS; e += 256) {
        const int w   = e / (64 * TAPS);
        const int rem = e % (64 * TAPS);
        const int c   = rem / TAPS;
        const int tap = rem % TAPS;
        const int ky  = tap / KS, kx = tap % KS;
        const int k   = (c0 + c) * TAPS + tap;
        out[((size_t)b * NPIX + h * 32 + w) * KTOT + permk(k)] =
            to_tf32(smv[(c * KS + ky) * 36 + (w + kx)]);
    }
}

// ---------------------------------------------------------------------------
// LayerNorm over channels, token-major [8192][256]. Warp per token.
// Output: tf32-rounded, k-permuted (GEMM A operand).
// ---------------------------------------------------------------------------
__global__ __launch_bounds__(256)
void ln_kernel(const float* __restrict__ x, const float* __restrict__ w,
               const float* __restrict__ bs, float* __restrict__ y)
{
    const int warp = threadIdx.x >> 5, lane = threadIdx.x & 31;
    const size_t tok = (size_t)blockIdx.x * 8 + warp;
    const float* xr = x + tok * CCH;
    float4 v0 = *(const float4*)(xr + lane * 4);
    float4 v1 = *(const float4*)(xr + 128 + lane * 4);
    float s  = v0.x + v0.y + v0.z + v0.w + v1.x + v1.y + v1.z + v1.w;
    float s2 = v0.x*v0.x + v0.y*v0.y + v0.z*v0.z + v0.w*v0.w
             + v1.x*v1.x + v1.y*v1.y + v1.z*v1.z + v1.w*v1.w;
#pragma unroll
    for (int o = 16; o > 0; o >>= 1) {
        s  += __shfl_xor_sync(0xffffffffu, s,  o);
        s2 += __shfl_xor_sync(0xffffffffu, s2, o);
    }
    const float mu = s * (1.f / 256.f);
    const float is = rsqrtf(s2 * (1.f / 256.f) - mu * mu + 1e-5f);
    float4 w0 = *(const float4*)(w + lane * 4);
    float4 w1 = *(const float4*)(w + 128 + lane * 4);
    float4 b0 = *(const float4*)(bs + lane * 4);
    float4 b1 = *(const float4*)(bs + 128 + lane * 4);
    float* yr = y + tok * CCH;
    float r0[4], r1[4];
    r0[0] = (v0.x - mu) * is * w0.x + b0.x; r0[1] = (v0.y - mu) * is * w0.y + b0.y;
    r0[2] = (v0.z - mu) * is * w0.z + b0.z; r0[3] = (v0.w - mu) * is * w0.w + b0.w;
    r1[0] = (v1.x - mu) * is * w1.x + b1.x; r1[1] = (v1.y - mu) * is * w1.y + b1.y;
    r1[2] = (v1.z - mu) * is * w1.z + b1.z; r1[3] = (v1.w - mu) * is * w1.w + b1.w;
#pragma unroll
    for (int j = 0; j < 4; j++) {
        yr[permk(lane * 4 + j)]       = to_tf32(r0[j]);
        yr[permk(128 + lane * 4 + j)] = to_tf32(r1[j]);
    }
}

// ---------------------------------------------------------------------------
// Flash attention, tf32 mma. qkv [B][1024][768] token-major (normal layout),
// out [B][1024][256] tf32-rounded k-PERMUTED (GEMM A operand).
// Block 128 queries / 8 warps; K/V tiles 64, double buffered.
// ---------------------------------------------------------------------------
__global__ __launch_bounds__(256, 1)
void attn_kernel(const float* __restrict__ qkv, float* __restrict__ out)
{
    float* sm = (float*)dyn_smem;
    float* Qs = sm;                      // [128][68]
    float* Ks = Qs + 128 * 68;           // [2][64][68]
    float* Vt = Ks + 2 * 64 * 68;        // [2][64][68]  (d, key)
    float* Ps = Vt + 2 * 64 * 68;        // [128][68]

    const int b = blockIdx.z, h = blockIdx.y;
    const int q0 = blockIdx.x * 128;
    const int hq = h * 64;
    const float* base = qkv + (size_t)b * NPIX * 768;

    const int t = threadIdx.x;
    const int wid = t >> 5, lane = t & 31;
    const int g = lane >> 2, tig = lane & 3;
    const int w16 = wid * 16;

#pragma unroll
    for (int i = 0; i < 8; i++) {
        const int e = t + i * 256;
        const int r = e >> 4, c = e & 15;
        float4 v = *(const float4*)(base + (size_t)(q0 + r) * 768 + hq + c * 4);
        Qs[r * 68 + c * 4 + 0] = to_tf32(v.x);
        Qs[r * 68 + c * 4 + 1] = to_tf32(v.y);
        Qs[r * 68 + c * 4 + 2] = to_tf32(v.z);
        Qs[r * 68 + c * 4 + 3] = to_tf32(v.w);
    }

    float oc[8][4];
#pragma unroll
    for (int n = 0; n < 8; n++)
#pragma unroll
        for (int c = 0; c < 4; c++) oc[n][c] = 0.f;
    float m0r = -1e30f, m1r = -1e30f, l0r = 0.f, l1r = 0.f;

    const int rkv = t & 63;
    float4 kvr[4], vvr[4];
#pragma unroll
    for (int i = 0; i < 4; i++) {
        const int e = t + i * 256;
        const int rk = e >> 4, ck = e & 15;
        kvr[i] = *(const float4*)(base + (size_t)rk * 768 + 256 + hq + ck * 4);
        const int cv = (t >> 6) + i * 4;
        vvr[i] = *(const float4*)(base + (size_t)rkv * 768 + 512 + hq + cv * 4);
    }
    {
        float* Kb = Ks;
        float* Vb = Vt;
#pragma unroll
        for (int i = 0; i < 4; i++) {
            const int e = t + i * 256;
            const int rk = e >> 4, ck = e & 15;
            Kb[rk * 68 + ck * 4 + 0] = to_tf32(kvr[i].x);
            Kb[rk * 68 + ck * 4 + 1] = to_tf32(kvr[i].y);
            Kb[rk * 68 + ck * 4 + 2] = to_tf32(kvr[i].z);
            Kb[rk * 68 + ck * 4 + 3] = to_tf32(kvr[i].w);
            const int cv = (t >> 6) + i * 4;
            Vb[(cv * 4 + 0) * 68 + rkv] = to_tf32(vvr[i].x);
            Vb[(cv * 4 + 1) * 68 + rkv] = to_tf32(vvr[i].y);
            Vb[(cv * 4 + 2) * 68 + rkv] = to_tf32(vvr[i].z);
            Vb[(cv * 4 + 3) * 68 + rkv] = to_tf32(vvr[i].w);
        }
    }
    __syncthreads();

    for (int tile = 0; tile < 16; tile++) {
        const int buf = tile & 1;
        float* Kb = Ks + buf * 64 * 68;
        float* Vb = Vt + buf * 64 * 68;

        if (tile < 15) {
            const size_t m0 = (size_t)(tile + 1) * 64;
#pragma unroll
            for (int i = 0; i < 4; i++) {
                const int e = t + i * 256;
                const int rk = e >> 4, ck = e & 15;
                kvr[i] = *(const float4*)(base + (m0 + rk) * 768 + 256 + hq + ck * 4);
                const int cv = (t >> 6) + i * 4;
                vvr[i] = *(const float4*)(base + (m0 + rkv) * 768 + 512 + hq + cv * 4);
            }
        }

        float s[8][4];
#pragma unroll
        for (int n = 0; n < 8; n++)
#pragma unroll
            for (int c = 0; c < 4; c++) s[n][c] = 0.f;
#pragma unroll
        for (int ks = 0; ks < 8; ks++) {
            const int k0 = ks * 8;
            const uint32_t a0 = __float_as_uint(Qs[(w16 + g) * 68 + k0 + tig]);
            const uint32_t a1 = __float_as_uint(Qs[(w16 + g + 8) * 68 + k0 + tig]);
            const uint32_t a2 = __float_as_uint(Qs[(w16 + g) * 68 + k0 + tig + 4]);
            const uint32_t a3 = __float_as_uint(Qs[(w16 + g + 8) * 68 + k0 + tig + 4]);
#pragma unroll
            for (int n = 0; n < 8; n++) {
                const uint32_t b0 = __float_as_uint(Kb[(n * 8 + g) * 68 + k0 + tig]);
                const uint32_t b1 = __float_as_uint(Kb[(n * 8 + g) * 68 + k0 + tig + 4]);
                MMA_TF32(s[n], a0, a1, a2, a3, b0, b1);
            }
        }

        float t0 = -1e30f, t1 = -1e30f;
#pragma unroll
        for (int n = 0; n < 8; n++) {
            s[n][0] *= 0.125f; s[n][1] *= 0.125f;
            s[n][2] *= 0.125f; s[n][3] *= 0.125f;
            t0 = fmaxf(t0, fmaxf(s[n][0], s[n][1]));
            t1 = fmaxf(t1, fmaxf(s[n][2], s[n][3]));
        }
        t0 = fmaxf(t0, __shfl_xor_sync(0xffffffffu, t0, 1));
        t0 = fmaxf(t0, __shfl_xor_sync(0xffffffffu, t0, 2));
        t1 = fmaxf(t1, __shfl_xor_sync(0xffffffffu, t1, 1));
        t1 = fmaxf(t1, __shfl_xor_sync(0xffffffffu, t1, 2));
        const float nm0 = fmaxf(m0r, t0), nm1 = fmaxf(m1r, t1);
        const float cr0 = __expf(m0r - nm0), cr1 = __expf(m1r - nm1);
        m0r = nm0; m1r = nm1;
        float ls0 = 0.f, ls1 = 0.f;
#pragma unroll
        for (int n = 0; n < 8; n++) {
            const float p0 = __expf(s[n][0] - nm0);
            const float p1 = __expf(s[n][1] - nm0);
            const float p2 = __expf(s[n][2] - nm1);
            const float p3 = __expf(s[n][3] - nm1);
            ls0 += p0 + p1; ls1 += p2 + p3;
            float2 pa; pa.x = to_tf32(p0); pa.y = to_tf32(p1);
            float2 pb; pb.x = to_tf32(p2); pb.y = to_tf32(p3);
            *(float2*)&Ps[(w16 + g) * 68 + n * 8 + tig * 2] = pa;
            *(float2*)&Ps[(w16 + g + 8) * 68 + n * 8 + tig * 2] = pb;
        }
        ls0 += __shfl_xor_sync(0xffffffffu, ls0, 1);
        ls0 += __shfl_xor_sync(0xffffffffu, ls0, 2);
        ls1 += __shfl_xor_sync(0xffffffffu, ls1, 1);
        ls1 += __shfl_xor_sync(0xffffffffu, ls1, 2);
        l0r = l0r * cr0 + ls0;
        l1r = l1r * cr1 + ls1;
#pragma unroll
        for (int n = 0; n < 8; n++) {
            oc[n][0] *= cr0; oc[n][1] *= cr0;
            oc[n][2] *= cr1; oc[n][3] *= cr1;
        }
        __syncwarp();

#pragma unroll
        for (int ks = 0; ks < 8; ks++) {
            const int k0 = ks * 8;
            const uint32_t a0 = __float_as_uint(Ps[(w16 + g) * 68 + k0 + tig]);
            const uint32_t a1 = __float_as_uint(Ps[(w16 + g + 8) * 68 + k0 + tig]);
            const uint32_t a2 = __float_as_uint(Ps[(w16 + g) * 68 + k0 + tig + 4]);
            const uint32_t a3 = __float_as_uint(Ps[(w16 + g + 8) * 68 + k0 + tig + 4]);
#pragma unroll
            for (int n = 0; n < 8; n++) {
                const uint32_t b0 = __float_as_uint(Vb[(n * 8 + g) * 68 + k0 + tig]);
                const uint32_t b1 = __float_as_uint(Vb[(n * 8 + g) * 68 + k0 + tig + 4]);
                MMA_TF32(oc[n], a0, a1, a2, a3, b0, b1);
            }
        }

        if (tile < 15) {
            __syncthreads();
            float* Kn = Ks + (buf ^ 1) * 64 * 68;
            float* Vn = Vt + (buf ^ 1) * 64 * 68;
#pragma unroll
            for (int i = 0; i < 4; i++) {
                const int e = t + i * 256;
                const int rk = e >> 4, ck = e & 15;
                Kn[rk * 68 + ck * 4 + 0] = to_tf32(kvr[i].x);
                Kn[rk * 68 + ck * 4 + 1] = to_tf32(kvr[i].y);
                Kn[rk * 68 + ck * 4 + 2] = to_tf32(kvr[i].z);
                Kn[rk * 68 + ck * 4 + 3] = to_tf32(kvr[i].w);
                const int cv = (t >> 6) + i * 4;
                Vn[(cv * 4 + 0) * 68 + rkv] = to_tf32(vvr[i].x);
                Vn[(cv * 4 + 1) * 68 + rkv] = to_tf32(vvr[i].y);
                Vn[(cv * 4 + 2) * 68 + rkv] = to_tf32(vvr[i].z);
                Vn[(cv * 4 + 3) * 68 + rkv] = to_tf32(vvr[i].w);
            }
            __syncthreads();
        }
    }

    // epilogue: permuted + tf32 (att feeds GEMM A).
    // local k = n*8 + 2*tig (+1) -> permuted positions P0, P0+2.
    const float i0 = 1.f / l0r, i1 = 1.f / l1r;
    const int P0 = ((tig & 1) << 2) | (tig >> 1);
    float* ob = out + (size_t)b * NPIX * CCH;
#pragma unroll
    for (int n = 0; n < 8; n++) {
        float* r0p = ob + (size_t)(q0 + w16 + g) * CCH + hq + n * 8;
        float* r1p = ob + (size_t)(q0 + w16 + g + 8) * CCH + hq + n * 8;
        r0p[P0]     = to_tf32(oc[n][0] * i0);
        r0p[P0 + 2] = to_tf32(oc[n][1] * i0);
        r1p[P0]     = to_tf32(oc[n][2] * i1);
        r1p[P0 + 2] = to_tf32(oc[n][3] * i1);
    }
}

// ---------------------------------------------------------------------------
// Depthwise 3x3 + exact GELU, token-major [8192][1024].
// Output tf32 + permuted (h2 feeds GEMM A).
// ---------------------------------------------------------------------------
__global__ __launch_bounds__(256)
void dwgelu_kernel(const float* __restrict__ x, const float* __restrict__ wd,
                   float* __restrict__ y)
{
    __shared__ float tile[10][34][32];
    const int c0 = blockIdx.x * 32;
    const int r0 = blockIdx.y * 8;
    const int b  = blockIdx.z;
    const int t  = threadIdx.x;
    const int ch = t & 31;

    for (int e = t; e < 10 * 34 * 32; e += 256) {
        const int cc  = e & 31;
        const int col = (e >> 5) % 34;
        const int r   = e / (34 * 32);
        const int hh = r0 + r - 1, ww = col - 1;
        float v = 0.f;
        if (hh >= 0 && hh < 32 && ww >= 0 && ww < 32)
            v = x[((size_t)b * NPIX + hh * 32 + ww) * HID + c0 + cc];
        tile[r][col][cc] = v;
    }
    float w9[9];
#pragma unroll
    for (int i = 0; i < 9; i++) w9[i] = wd[(size_t)(c0 + ch) * 9 + i];
    const int pc = permk(c0 + ch);
    __syncthreads();

    for (int e = t; e < 8 * 32 * 32; e += 256) {
        const int w = (e >> 5) & 31;
        const int r = e >> 10;
        float a = 0.f;
#pragma unroll
        for (int ky = 0; ky < 3; ky++)
#pragma unroll
            for (int kx = 0; kx < 3; kx++)
                a += w9[ky * 3 + kx] * tile[r + ky][w + kx][ch];
        y[((size_t)b * NPIX + (r0 + r) * 32 + w) * HID + pc] =
            to_tf32(0.5f * a * (1.f + erff(a * 0.70710678118654752f)));
    }
}

// ---------------------------------------------------------------------------
extern "C" void kernel_launch(void* const* d_in, const int* in_sizes, int n_in,
                              void* d_out, int out_size)
{
    const float* aop      = (const float*)d_in[0];
    const float* dop      = (const float*)d_in[1];
    const float* w_qconv  = (const float*)d_in[2];
    const float* w_kvconv = (const float*)d_in[3];
    const float* lnq1_w   = (const float*)d_in[4];
    const float* lnq1_b   = (const float*)d_in[5];
    const float* lnkv1_w  = (const float*)d_in[6];
    const float* lnkv1_b  = (const float*)d_in[7];
    const float* lnq2_w   = (const float*)d_in[8];
    const float* lnq2_b   = (const float*)d_in[9];
    const float* lnkv2_w  = (const float*)d_in[10];
    const float* lnkv2_b  = (const float*)d_in[11];
    const float* lnffn_w  = (const float*)d_in[12];
    const float* lnffn_b  = (const float*)d_in[13];
    const float* saq_qkv  = (const float*)d_in[14];
    const float* saq_proj = (const float*)d_in[15];
    const float* sakv_qkv = (const float*)d_in[16];
    const float* sakv_proj= (const float*)d_in[17];
    const float* ca_q     = (const float*)d_in[18];
    const float* ca_k     = (const float*)d_in[19];
    const float* ca_v     = (const float*)d_in[20];
    const float* ca_proj  = (const float*)d_in[21];
    const float* leff_in  = (const float*)d_in[22];
    const float* leff_dw  = (const float*)d_in[23];
    const float* leff_out = (const float*)d_in[24];
    float* out = (float*)d_out;

    float* S = nullptr;
    cudaGetSymbolAddress((void**)&S, g_scratch);
    float* ic   = S;
    float* qb   = ic   + IC_SZ;
    float* kvb  = qb   + C_SZ;
    float* lnb  = kvb  + C_SZ;
    float* qn   = lnb  + C_SZ;
    float* kvn  = qn   + C_SZ;
    float* att  = kvn  + C_SZ;
    float* xbuf = att  + C_SZ;
    float* qkv  = xbuf + C_SZ;
    float* h1   = qkv  + QKV_SZ;
    float* h2   = h1   + H_SZ;
    float* wp   = h2   + H_SZ;

    // permuted tf32 weight copies
    float* p_wq3   = wp;                     // 589824
    float* p_wk5   = p_wq3   + 589824;       // 1638400
    float* p_saqkv = p_wk5   + 1638400;      // 196608
    float* p_saprj = p_saqkv + 196608;       // 65536
    float* p_skqkv = p_saprj + 65536;        // 196608
    float* p_skprj = p_skqkv + 196608;       // 65536
    float* p_caq   = p_skprj + 65536;
    float* p_cak   = p_caq   + 65536;
    float* p_cav   = p_cak   + 65536;
    float* p_caprj = p_cav   + 65536;
    float* p_lin   = p_caprj + 65536;        // 262144
    float* p_lout  = p_lin   + 262144;       // 262144

    const int GEMM_SM = 2 * 5120 * 2 * 4;    // 81920
    const int ATTN_SM = (128 * 68 + 2 * 64 * 68 + 2 * 64 * 68 + 128 * 68) * 4; // 139264
    cudaFuncSetAttribute(gemm_tc,     cudaFuncAttributeMaxDynamicSharedMemorySize, GEMM_SM);
    cudaFuncSetAttribute(attn_kernel, cudaFuncAttributeMaxDynamicSharedMemorySize, ATTN_SM);

    // weight prep
    prep_w<<<(589824 + 255) / 256, 256>>>(w_qconv,  p_wq3,   589824);
    prep_w<<<(1638400 + 255) / 256, 256>>>(w_kvconv, p_wk5,  1638400);
    prep_w<<<(196608 + 255) / 256, 256>>>(saq_qkv,  p_saqkv, 196608);
    prep_w<<<(65536 + 255) / 256, 256>>>(saq_proj,  p_saprj, 65536);
    prep_w<<<(196608 + 255) / 256, 256>>>(sakv_qkv, p_skqkv, 196608);
    prep_w<<<(65536 + 255) / 256, 256>>>(sakv_proj, p_skprj, 65536);
    prep_w<<<(65536 + 255) / 256, 256>>>(ca_q,      p_caq,   65536);
    prep_w<<<(65536 + 255) / 256, 256>>>(ca_k,      p_cak,   65536);
    prep_w<<<(65536 + 255) / 256, 256>>>(ca_v,      p_cav,   65536);
    prep_w<<<(65536 + 255) / 256, 256>>>(ca_proj,   p_caprj, 65536);
    prep_w<<<(262144 + 255) / 256, 256>>>(leff_in,  p_lin,   262144);
    prep_w<<<(262144 + 255) / 256, 256>>>(leff_out, p_lout,  262144);

    const dim3 g256(8, 2, B_), g768(8, 6, B_), g1024t(8, 8, B_);
    const dim3 gattn(8, 4, B_);
    const dim3 gi2c(4, 32, B_);
    const dim3 gdw(32, 4, B_);

    // ---- q branch ----
    im2col_kernel<3><<<gi2c, 256>>>(aop, ic);
    gemm_tc<<<g256, 256, GEMM_SM>>>(ic, 2304, p_wq3, nullptr, 0, qb, 256, 2304, 0);
    ln_kernel<<<1024, 256>>>(qb, lnq1_w, lnq1_b, lnb);
    gemm_tc<<<g768, 256, GEMM_SM>>>(lnb, 256, p_saqkv, nullptr, 0, qkv, 768, 256, 0);
    attn_kernel<<<gattn, 256, ATTN_SM>>>(qkv, att);
    gemm_tc<<<g256, 256, GEMM_SM>>>(att, 256, p_saprj, qb, 256, qb, 256, 256, 0);
    ln_kernel<<<1024, 256>>>(qb, lnq2_w, lnq2_b, qn);

    // ---- kv branch ----
    im2col_kernel<5><<<gi2c, 256>>>(dop, ic);
    gemm_tc<<<g256, 256, GEMM_SM>>>(ic, 6400, p_wk5, nullptr, 0, kvb, 256, 6400, 0);
    ln_kernel<<<1024, 256>>>(kvb, lnkv1_w, lnkv1_b, lnb);
    gemm_tc<<<g768, 256, GEMM_SM>>>(lnb, 256, p_skqkv, nullptr, 0, qkv, 768, 256, 0);
    attn_kernel<<<gattn, 256, ATTN_SM>>>(qkv, att);
    gemm_tc<<<g256, 256, GEMM_SM>>>(att, 256, p_skprj, kvb, 256, kvb, 256, 256, 0);
    ln_kernel<<<1024, 256>>>(kvb, lnkv2_w, lnkv2_b, kvn);

    // ---- cross attention ----
    gemm_tc<<<g256, 256, GEMM_SM>>>(qn,  256, p_caq,   nullptr, 0, qkv,       768, 256, 0);
    gemm_tc<<<g256, 256, GEMM_SM>>>(kvn, 256, p_cak,   nullptr, 0, qkv + 256, 768, 256, 0);
    gemm_tc<<<g256, 256, GEMM_SM>>>(kvn, 256, p_cav,   nullptr, 0, qkv + 512, 768, 256, 0);
    attn_kernel<<<gattn, 256, ATTN_SM>>>(qkv, att);
    gemm_tc<<<g256, 256, GEMM_SM>>>(att, 256, p_caprj, qb, 256, xbuf, 256, 256, 0);

    // ---- LeFF ----
    ln_kernel<<<1024, 256>>>(xbuf, lnffn_w, lnffn_b, lnb);
    gemm_tc<<<g1024t, 256, GEMM_SM>>>(lnb, 256, p_lin, nullptr, 0, h1, 1024, 256, 0);
    dwgelu_kernel<<<gdw, 256>>>(h1, leff_dw, h2);
    gemm_tc<<<g256, 256, GEMM_SM>>>(h2, 1024, p_lout, xbuf, 256, out, 256, 1024, 1);
}